// round 4
// baseline (speedup 1.0000x reference)
#include <cuda_runtime.h>
#include <math.h>

#define NN 20000
#define EE 160000
#define OUTD 256
#define INDIM 256
#define NH 8

typedef unsigned long long ull;

// ---------------- scratch (device globals; no allocation allowed) ----------------
__device__ float g_K[NN * OUTD];
__device__ float g_Q[NN * OUTD];
__device__ float g_V[NN * OUTD];
__device__ float g_MK[NN * OUTD];
__device__ float g_VAL[3 * NN * OUTD];
__device__ float g_CVAL[3 * NN * OUTD];
// CSR by destination node, per etype
__device__ int g_cnt[3 * NN];
__device__ int g_ptr[3 * (NN + 1)];
__device__ int g_cur[3 * NN];
__device__ int g_srcs[3 * EE];

// ---------------- f32x2 helpers ----------------
__device__ __forceinline__ ull pack2(float a, float b) {
    ull r; asm("mov.b64 %0, {%1, %2};" : "=l"(r) : "f"(a), "f"(b)); return r;
}
__device__ __forceinline__ void fma2(ull& acc, ull a, ull b) {
    asm("fma.rn.f32x2 %0, %1, %2, %0;" : "+l"(acc) : "l"(a), "l"(b));
}
__device__ __forceinline__ float2 unpack2(ull v) {
    float2 f; asm("mov.b64 {%0, %1}, %2;" : "=f"(f.x), "=f"(f.y) : "l"(v)); return f;
}
__device__ __forceinline__ float dot4(float4 a, float4 b) {
    return a.x * b.x + a.y * b.y + a.z * b.z + a.w * b.w;
}

// ---------------- kernel 1: fused QKV GEMM (f32x2) ----------------
#define BM 128
#define BN 128
#define BK 8
__global__ void __launch_bounds__(256) gemm_qkv(
    const float* __restrict__ x,
    const float* __restrict__ Wk, const float* __restrict__ bk,
    const float* __restrict__ Wq, const float* __restrict__ bq,
    const float* __restrict__ Wv, const float* __restrict__ bv)
{
    __shared__ float As[BK][BM + 4];
    __shared__ float Bs[BK][BN + 4];

    int t = threadIdx.x;
    int tx = t & 15, ty = t >> 4;
    int rowBase = blockIdx.y * BM;
    int cb = blockIdx.x * BN;

    const float* W; const float* bias; float* out;
    if (cb < 256)      { W = Wk; bias = bk; out = g_K; }
    else if (cb < 512) { W = Wq; bias = bq; out = g_Q; cb -= 256; }
    else               { W = Wv; bias = bv; out = g_V; cb -= 512; }

    int ar = t >> 1;
    int ak = (t & 1) * 4;
    int bkr = t >> 5;
    int bc  = (t & 31) * 4;

    ull acc[4][8];
#pragma unroll
    for (int i = 0; i < 4; i++)
#pragma unroll
        for (int j = 0; j < 8; j++) acc[i][j] = 0ull;

    for (int k0 = 0; k0 < INDIM; k0 += BK) {
        float4 av = make_float4(0.f, 0.f, 0.f, 0.f);
        int gr = rowBase + ar;
        if (gr < NN) av = *(const float4*)&x[gr * INDIM + k0 + ak];
        As[ak + 0][ar] = av.x;
        As[ak + 1][ar] = av.y;
        As[ak + 2][ar] = av.z;
        As[ak + 3][ar] = av.w;

        *(float4*)&Bs[bkr][bc] = *(const float4*)&W[(k0 + bkr) * 256 + cb + bc];
        __syncthreads();

#pragma unroll
        for (int kk = 0; kk < BK; kk++) {
            ull a2[4];
#pragma unroll
            for (int i = 0; i < 4; i++)
                a2[i] = *(const ull*)&As[kk][ty * 8 + 2 * i];
            float4 b0 = *(const float4*)&Bs[kk][tx * 8];
            float4 b1 = *(const float4*)&Bs[kk][tx * 8 + 4];
            ull bb[8];
            bb[0] = pack2(b0.x, b0.x); bb[1] = pack2(b0.y, b0.y);
            bb[2] = pack2(b0.z, b0.z); bb[3] = pack2(b0.w, b0.w);
            bb[4] = pack2(b1.x, b1.x); bb[5] = pack2(b1.y, b1.y);
            bb[6] = pack2(b1.z, b1.z); bb[7] = pack2(b1.w, b1.w);
#pragma unroll
            for (int i = 0; i < 4; i++)
#pragma unroll
                for (int j = 0; j < 8; j++)
                    fma2(acc[i][j], a2[i], bb[j]);
        }
        __syncthreads();
    }

    int c0 = cb + tx * 8;
    float4 bias0 = *(const float4*)&bias[c0];
    float4 bias1 = *(const float4*)&bias[c0 + 4];

#pragma unroll
    for (int i2 = 0; i2 < 4; i2++) {
        float2 u[8];
#pragma unroll
        for (int j = 0; j < 8; j++) u[j] = unpack2(acc[i2][j]);
        int r0 = rowBase + ty * 8 + 2 * i2;
        if (r0 < NN) {
            float4 o0 = make_float4(u[0].x + bias0.x, u[1].x + bias0.y,
                                    u[2].x + bias0.z, u[3].x + bias0.w);
            float4 o1 = make_float4(u[4].x + bias1.x, u[5].x + bias1.y,
                                    u[6].x + bias1.z, u[7].x + bias1.w);
            *(float4*)&out[r0 * OUTD + c0] = o0;
            *(float4*)&out[r0 * OUTD + c0 + 4] = o1;
        }
        if (r0 + 1 < NN) {
            float4 o0 = make_float4(u[0].y + bias0.x, u[1].y + bias0.y,
                                    u[2].y + bias0.z, u[3].y + bias0.w);
            float4 o1 = make_float4(u[4].y + bias1.x, u[5].y + bias1.y,
                                    u[6].y + bias1.z, u[7].y + bias1.w);
            *(float4*)&out[(r0 + 1) * OUTD + c0] = o0;
            *(float4*)&out[(r0 + 1) * OUTD + c0 + 4] = o1;
        }
    }
}

// ---------------- kernel 2: node-level relation transforms ----------------
__global__ void __launch_bounds__(288) transform_kernel(
    const float* __restrict__ msg, const float* __restrict__ msg_cau,
    const float* __restrict__ cau_filter, const float* __restrict__ time_emb,
    const int* __restrict__ cau_type)
{
    __shared__ float k_s[32][32];
    __shared__ float v_s[32][32];
    __shared__ float vt_s[32][32];
    __shared__ int ct_s[32];

    int h = blockIdx.y;
    int nodeBase = blockIdx.x * 32;
    int tid = threadIdx.x;

    for (int idx = tid; idx < 32 * 32; idx += 288) {
        int n = idx >> 5, dcol = idx & 31;
        int gn = nodeBase + n;
        float kv = 0.f, vv = 0.f;
        if (gn < NN) {
            kv = g_K[gn * OUTD + h * 32 + dcol];
            vv = g_V[gn * OUTD + h * 32 + dcol];
        }
        k_s[n][dcol] = kv;
        v_s[n][dcol] = vv;
        vt_s[n][dcol] = vv + time_emb[h * 32 + dcol];
    }
    for (int idx = tid; idx < 32; idx += 288) {
        int gn = nodeBase + idx;
        ct_s[idx] = (gn < NN) ? cau_type[gn] : -1;
    }
    __syncthreads();

    int wid = tid >> 5, lane = tid & 31;
    const float* mat;
    const float (*srcm)[32];
    float* outp;
    int myct = -1;
    if (wid < 3) {
        mat = cau_filter + (wid * NH + h) * 1024;
        srcm = k_s; outp = g_MK; myct = wid;
    } else if (wid < 6) {
        int e = wid - 3;
        mat = msg + (e * NH + h) * 1024;
        srcm = v_s; outp = g_VAL + e * NN * OUTD;
    } else {
        int e = wid - 6;
        mat = msg_cau + (e * NH + h) * 1024;
        srcm = vt_s; outp = g_CVAL + e * NN * OUTD;
    }

    ull m2[16];
#pragma unroll
    for (int i = 0; i < 16; i++)
        m2[i] = pack2(mat[(2 * i) * 32 + lane], mat[(2 * i + 1) * 32 + lane]);

    for (int n = 0; n < 32; n++) {
        int gn = nodeBase + n;
        if (gn >= NN) break;
        if (myct >= 0 && ct_s[n] != myct) continue;
        ull acc = 0ull;
        const ull* row = (const ull*)&srcm[n][0];
#pragma unroll
        for (int i = 0; i < 16; i++)
            fma2(acc, row[i], m2[i]);
        float2 f = unpack2(acc);
        outp[gn * OUTD + h * 32 + lane] = f.x + f.y;
    }
}

// ---------------- CSR build ----------------
__global__ void zero_cnt_kernel() {
    int i = blockIdx.x * blockDim.x + threadIdx.x;
    if (i < 3 * NN) g_cnt[i] = 0;
}

__global__ void hist_kernel(const int* __restrict__ dst) {
    int stride = gridDim.x * blockDim.x;
    for (int i = blockIdx.x * blockDim.x + threadIdx.x; i < 3 * EE; i += stride) {
        int e = i / EE;
        int d = dst[i];
        atomicAdd(&g_cnt[e * NN + d], 1);
    }
}

__global__ void __launch_bounds__(1024) scan_kernel() {
    int e = blockIdx.x;
    int tid = threadIdx.x;
    int lane = tid & 31, wid = tid >> 5;
    __shared__ int wsum[32];
    int carry = 0;

    for (int chunk = 0; chunk < NN; chunk += 1024) {
        int i = chunk + tid;
        int v = (i < NN) ? g_cnt[e * NN + i] : 0;
        int x = v;
#pragma unroll
        for (int sh = 1; sh < 32; sh <<= 1) {
            int y = __shfl_up_sync(0xffffffffu, x, sh);
            if (lane >= sh) x += y;
        }
        if (lane == 31) wsum[wid] = x;
        __syncthreads();
        if (wid == 0) {
            int t2 = wsum[lane];
#pragma unroll
            for (int sh = 1; sh < 32; sh <<= 1) {
                int y = __shfl_up_sync(0xffffffffu, t2, sh);
                if (lane >= sh) t2 += y;
            }
            wsum[lane] = t2;
        }
        __syncthreads();
        int incl = x + (wid ? wsum[wid - 1] : 0);
        int excl = incl - v + carry;
        if (i < NN) {
            g_ptr[e * (NN + 1) + i] = excl;
            g_cur[e * NN + i] = excl;
        }
        carry += wsum[31];
        __syncthreads();
    }
    if (tid == 0) g_ptr[e * (NN + 1) + NN] = carry;
}

__global__ void scatter_kernel(const int* __restrict__ src, const int* __restrict__ dst) {
    int stride = gridDim.x * blockDim.x;
    for (int i = blockIdx.x * blockDim.x + threadIdx.x; i < 3 * EE; i += stride) {
        int e = i / EE;
        int d = dst[i];
        int s = src[i];
        int pos = atomicAdd(&g_cur[e * NN + d], 1);
        g_srcs[e * EE + pos] = s;
    }
}

// ---------------- fused softmax + aggregation: one warp per dst node ----------------
// Single pass: no segment-max needed (logits O(1)); accumulate numerator and
// denominator online. q[d] loaded once. Output written with a plain store.
__global__ void __launch_bounds__(256) fused_edge_kernel(
    const float* __restrict__ pri, const float* __restrict__ pri_cau,
    const float* __restrict__ comb_pri, float* __restrict__ out)
{
    int d = blockIdx.x * 8 + (threadIdx.x >> 5);
    int lane = threadIdx.x & 31;
    int off = lane * 4;
    int g = lane >> 3;
    const float isdk = 0.17677669529663687f;  // 1/sqrt(32)

    const float* qp = g_Q + d * OUTD;
    float4 qa = *(const float4*)(qp + off);
    float4 qb = *(const float4*)(qp + 128 + off);

    float4 ra = make_float4(0.f, 0.f, 0.f, 0.f);
    float4 rb = make_float4(0.f, 0.f, 0.f, 0.f);

#pragma unroll
    for (int e = 0; e < 3; e++) {
        int beg = g_ptr[e * (NN + 1) + d];
        int end = g_ptr[e * (NN + 1) + d + 1];
        if (beg == end) continue;

        float pr0 = pri[e * NH + g] * isdk;
        float pr1 = pri[e * NH + g + 4] * isdk;
        float pc0 = pri_cau[e * NH + g] * isdk;
        float pc1 = pri_cau[e * NH + g + 4] * isdk;

        float4 aa = make_float4(0.f, 0.f, 0.f, 0.f);
        float4 ab = make_float4(0.f, 0.f, 0.f, 0.f);
        float4 ca = make_float4(0.f, 0.f, 0.f, 0.f);
        float4 cb2 = make_float4(0.f, 0.f, 0.f, 0.f);
        float sa0 = 0.f, sa1 = 0.f, sc0 = 0.f, sc1 = 0.f;

        const int* sl = g_srcs + e * EE;
        const float* valb = g_VAL + e * NN * OUTD;
        const float* cvalb = g_CVAL + e * NN * OUTD;

        for (int i = beg; i < end; i++) {
            int s = sl[i];
            const float* kp = g_K + s * OUTD;
            const float* mp = g_MK + s * OUTD;
            float4 k0 = *(const float4*)(kp + off);
            float4 k1 = *(const float4*)(kp + 128 + off);
            float4 m0 = *(const float4*)(mp + off);
            float4 m1 = *(const float4*)(mp + 128 + off);

            float p0 = dot4(qa, k0);
            float p1 = dot4(qb, k1);
            float t0 = dot4(qa, m0);
            float t1 = dot4(qb, m1);
#pragma unroll
            for (int sh = 1; sh <= 4; sh <<= 1) {
                p0 += __shfl_xor_sync(0xffffffffu, p0, sh);
                p1 += __shfl_xor_sync(0xffffffffu, p1, sh);
                t0 += __shfl_xor_sync(0xffffffffu, t0, sh);
                t1 += __shfl_xor_sync(0xffffffffu, t1, sh);
            }
            float ea0 = __expf(p0 * pr0);
            float ea1 = __expf(p1 * pr1);
            float ec0 = __expf(t0 * pc0);
            float ec1 = __expf(t1 * pc1);
            sa0 += ea0; sa1 += ea1; sc0 += ec0; sc1 += ec1;

            const float* vp = valb + s * OUTD;
            const float* cp = cvalb + s * OUTD;
            float4 v0 = *(const float4*)(vp + off);
            float4 v1 = *(const float4*)(vp + 128 + off);
            float4 c0 = *(const float4*)(cp + off);
            float4 c1 = *(const float4*)(cp + 128 + off);

            aa.x += ea0 * v0.x; aa.y += ea0 * v0.y; aa.z += ea0 * v0.z; aa.w += ea0 * v0.w;
            ab.x += ea1 * v1.x; ab.y += ea1 * v1.y; ab.z += ea1 * v1.z; ab.w += ea1 * v1.w;
            ca.x += ec0 * c0.x; ca.y += ec0 * c0.y; ca.z += ec0 * c0.z; ca.w += ec0 * c0.w;
            cb2.x += ec1 * c1.x; cb2.y += ec1 * c1.y; cb2.z += ec1 * c1.z; cb2.w += ec1 * c1.w;
        }

        float isa0 = __fdividef(1.f, sa0);
        float isa1 = __fdividef(1.f, sa1);
        float isc0 = __fdividef(1.f, sc0);
        float isc1 = __fdividef(1.f, sc1);
        float4 b0 = *(const float4*)&comb_pri[e * OUTD + off];
        float4 b1 = *(const float4*)&comb_pri[e * OUTD + 128 + off];

        ra.x += aa.x * isa0 + ca.x * isc0 * b0.x;
        ra.y += aa.y * isa0 + ca.y * isc0 * b0.y;
        ra.z += aa.z * isa0 + ca.z * isc0 * b0.z;
        ra.w += aa.w * isa0 + ca.w * isc0 * b0.w;
        rb.x += ab.x * isa1 + cb2.x * isc1 * b1.x;
        rb.y += ab.y * isa1 + cb2.y * isc1 * b1.y;
        rb.z += ab.z * isa1 + cb2.z * isc1 * b1.z;
        rb.w += ab.w * isa1 + cb2.w * isc1 * b1.w;
    }

    const float third = 1.0f / 3.0f;
    float4 oa = make_float4(fmaxf(ra.x * third, 0.f), fmaxf(ra.y * third, 0.f),
                            fmaxf(ra.z * third, 0.f), fmaxf(ra.w * third, 0.f));
    float4 ob = make_float4(fmaxf(rb.x * third, 0.f), fmaxf(rb.y * third, 0.f),
                            fmaxf(rb.z * third, 0.f), fmaxf(rb.w * third, 0.f));
    *(float4*)(out + d * OUTD + off) = oa;
    *(float4*)(out + d * OUTD + 128 + off) = ob;
}

// ---------------- launch ----------------
extern "C" void kernel_launch(void* const* d_in, const int* in_sizes, int n_in,
                              void* d_out, int out_size) {
    const float* x          = (const float*)d_in[0];
    const float* Wk         = (const float*)d_in[1];
    const float* bk         = (const float*)d_in[2];
    const float* Wq         = (const float*)d_in[3];
    const float* bq         = (const float*)d_in[4];
    const float* Wv         = (const float*)d_in[5];
    const float* bv         = (const float*)d_in[6];
    const float* pri        = (const float*)d_in[7];
    const float* msg        = (const float*)d_in[8];
    const float* pri_cau    = (const float*)d_in[9];
    const float* msg_cau    = (const float*)d_in[10];
    const float* comb_pri   = (const float*)d_in[11];
    const float* cau_filter = (const float*)d_in[12];
    const float* time_emb   = (const float*)d_in[13];
    const int*   cau_type   = (const int*)d_in[14];
    const int*   src        = (const int*)d_in[15];
    const int*   dst        = (const int*)d_in[16];
    float* out = (float*)d_out;

    // CSR build (independent of gemm/transform; launch first)
    zero_cnt_kernel<<<(3 * NN + 255) / 256, 256>>>();
    hist_kernel<<<512, 256>>>(dst);
    scan_kernel<<<3, 1024>>>();
    scatter_kernel<<<512, 256>>>(src, dst);

    dim3 ggrid(768 / BN, (NN + BM - 1) / BM);
    gemm_qkv<<<ggrid, 256>>>(x, Wk, bk, Wq, bq, Wv, bv);

    dim3 tgrid((NN + 31) / 32, NH);
    transform_kernel<<<tgrid, 288>>>(msg, msg_cau, cau_filter, time_emb, cau_type);

    fused_edge_kernel<<<NN / 8, 256>>>(pri, pri_cau, comb_pri, out);
}

// round 5
// speedup vs baseline: 1.0354x; 1.0354x over previous
#include <cuda_runtime.h>
#include <math.h>

#define NN 20000
#define EE 160000
#define OUTD 256
#define INDIM 256
#define NH 8

typedef unsigned long long ull;

// ---------------- scratch (device globals; no allocation allowed) ----------------
__device__ float g_K[NN * OUTD];
__device__ float g_Q[NN * OUTD];
__device__ float g_V[NN * OUTD];
__device__ float g_MK[NN * OUTD];
__device__ float g_VAL[3 * NN * OUTD];
__device__ float g_CVAL[3 * NN * OUTD];
// CSR by destination node, per etype
__device__ int g_cnt[3 * NN];
__device__ int g_ptr[3 * (NN + 1)];
__device__ int g_cur[3 * NN];
__device__ int g_esrc[3 * EE];           // src id per CSR slot
__device__ float2 g_E[3 * EE * NH];      // (ea, eca) per CSR slot * head
__device__ float2 g_S[3 * NN * NH];      // (sum_ea, sum_eca) per dst-head

// ---------------- f32x2 helpers ----------------
__device__ __forceinline__ ull pack2(float a, float b) {
    ull r; asm("mov.b64 %0, {%1, %2};" : "=l"(r) : "f"(a), "f"(b)); return r;
}
__device__ __forceinline__ void fma2(ull& acc, ull a, ull b) {
    asm("fma.rn.f32x2 %0, %1, %2, %0;" : "+l"(acc) : "l"(a), "l"(b));
}
__device__ __forceinline__ float2 unpack2(ull v) {
    float2 f; asm("mov.b64 {%0, %1}, %2;" : "=f"(f.x), "=f"(f.y) : "l"(v)); return f;
}
__device__ __forceinline__ float dot4(float4 a, float4 b) {
    return a.x * b.x + a.y * b.y + a.z * b.z + a.w * b.w;
}
__device__ __forceinline__ void red_add_v2(float2* p, float a, float b) {
    asm volatile("red.global.add.v2.f32 [%0], {%1,%2};"
                 :: "l"(p), "f"(a), "f"(b) : "memory");
}

// ---------------- kernel 1: fused QKV GEMM (f32x2) ----------------
#define BM 128
#define BN 128
#define BK 8
__global__ void __launch_bounds__(256) gemm_qkv(
    const float* __restrict__ x,
    const float* __restrict__ Wk, const float* __restrict__ bk,
    const float* __restrict__ Wq, const float* __restrict__ bq,
    const float* __restrict__ Wv, const float* __restrict__ bv)
{
    __shared__ float As[BK][BM + 4];
    __shared__ float Bs[BK][BN + 4];

    int t = threadIdx.x;
    int tx = t & 15, ty = t >> 4;
    int rowBase = blockIdx.y * BM;
    int cb = blockIdx.x * BN;

    const float* W; const float* bias; float* out;
    if (cb < 256)      { W = Wk; bias = bk; out = g_K; }
    else if (cb < 512) { W = Wq; bias = bq; out = g_Q; cb -= 256; }
    else               { W = Wv; bias = bv; out = g_V; cb -= 512; }

    int ar = t >> 1;
    int ak = (t & 1) * 4;
    int bkr = t >> 5;
    int bc  = (t & 31) * 4;

    ull acc[4][8];
#pragma unroll
    for (int i = 0; i < 4; i++)
#pragma unroll
        for (int j = 0; j < 8; j++) acc[i][j] = 0ull;

    for (int k0 = 0; k0 < INDIM; k0 += BK) {
        float4 av = make_float4(0.f, 0.f, 0.f, 0.f);
        int gr = rowBase + ar;
        if (gr < NN) av = *(const float4*)&x[gr * INDIM + k0 + ak];
        As[ak + 0][ar] = av.x;
        As[ak + 1][ar] = av.y;
        As[ak + 2][ar] = av.z;
        As[ak + 3][ar] = av.w;

        *(float4*)&Bs[bkr][bc] = *(const float4*)&W[(k0 + bkr) * 256 + cb + bc];
        __syncthreads();

#pragma unroll
        for (int kk = 0; kk < BK; kk++) {
            ull a2[4];
#pragma unroll
            for (int i = 0; i < 4; i++)
                a2[i] = *(const ull*)&As[kk][ty * 8 + 2 * i];
            float4 b0 = *(const float4*)&Bs[kk][tx * 8];
            float4 b1 = *(const float4*)&Bs[kk][tx * 8 + 4];
            ull bb[8];
            bb[0] = pack2(b0.x, b0.x); bb[1] = pack2(b0.y, b0.y);
            bb[2] = pack2(b0.z, b0.z); bb[3] = pack2(b0.w, b0.w);
            bb[4] = pack2(b1.x, b1.x); bb[5] = pack2(b1.y, b1.y);
            bb[6] = pack2(b1.z, b1.z); bb[7] = pack2(b1.w, b1.w);
#pragma unroll
            for (int i = 0; i < 4; i++)
#pragma unroll
                for (int j = 0; j < 8; j++)
                    fma2(acc[i][j], a2[i], bb[j]);
        }
        __syncthreads();
    }

    int c0 = cb + tx * 8;
    float4 bias0 = *(const float4*)&bias[c0];
    float4 bias1 = *(const float4*)&bias[c0 + 4];

#pragma unroll
    for (int i2 = 0; i2 < 4; i2++) {
        float2 u[8];
#pragma unroll
        for (int j = 0; j < 8; j++) u[j] = unpack2(acc[i2][j]);
        int r0 = rowBase + ty * 8 + 2 * i2;
        if (r0 < NN) {
            float4 o0 = make_float4(u[0].x + bias0.x, u[1].x + bias0.y,
                                    u[2].x + bias0.z, u[3].x + bias0.w);
            float4 o1 = make_float4(u[4].x + bias1.x, u[5].x + bias1.y,
                                    u[6].x + bias1.z, u[7].x + bias1.w);
            *(float4*)&out[r0 * OUTD + c0] = o0;
            *(float4*)&out[r0 * OUTD + c0 + 4] = o1;
        }
        if (r0 + 1 < NN) {
            float4 o0 = make_float4(u[0].y + bias0.x, u[1].y + bias0.y,
                                    u[2].y + bias0.z, u[3].y + bias0.w);
            float4 o1 = make_float4(u[4].y + bias1.x, u[5].y + bias1.y,
                                    u[6].y + bias1.z, u[7].y + bias1.w);
            *(float4*)&out[(r0 + 1) * OUTD + c0] = o0;
            *(float4*)&out[(r0 + 1) * OUTD + c0 + 4] = o1;
        }
    }
}

// ---------------- kernel 2: node-level relation transforms ----------------
__global__ void __launch_bounds__(288) transform_kernel(
    const float* __restrict__ msg, const float* __restrict__ msg_cau,
    const float* __restrict__ cau_filter, const float* __restrict__ time_emb,
    const int* __restrict__ cau_type)
{
    __shared__ float k_s[32][32];
    __shared__ float v_s[32][32];
    __shared__ float vt_s[32][32];
    __shared__ int ct_s[32];

    int h = blockIdx.y;
    int nodeBase = blockIdx.x * 32;
    int tid = threadIdx.x;

    for (int idx = tid; idx < 32 * 32; idx += 288) {
        int n = idx >> 5, dcol = idx & 31;
        int gn = nodeBase + n;
        float kv = 0.f, vv = 0.f;
        if (gn < NN) {
            kv = g_K[gn * OUTD + h * 32 + dcol];
            vv = g_V[gn * OUTD + h * 32 + dcol];
        }
        k_s[n][dcol] = kv;
        v_s[n][dcol] = vv;
        vt_s[n][dcol] = vv + time_emb[h * 32 + dcol];
    }
    for (int idx = tid; idx < 32; idx += 288) {
        int gn = nodeBase + idx;
        ct_s[idx] = (gn < NN) ? cau_type[gn] : -1;
    }
    __syncthreads();

    int wid = tid >> 5, lane = tid & 31;
    const float* mat;
    const float (*srcm)[32];
    float* outp;
    int myct = -1;
    if (wid < 3) {
        mat = cau_filter + (wid * NH + h) * 1024;
        srcm = k_s; outp = g_MK; myct = wid;
    } else if (wid < 6) {
        int e = wid - 3;
        mat = msg + (e * NH + h) * 1024;
        srcm = v_s; outp = g_VAL + e * NN * OUTD;
    } else {
        int e = wid - 6;
        mat = msg_cau + (e * NH + h) * 1024;
        srcm = vt_s; outp = g_CVAL + e * NN * OUTD;
    }

    ull m2[16];
#pragma unroll
    for (int i = 0; i < 16; i++)
        m2[i] = pack2(mat[(2 * i) * 32 + lane], mat[(2 * i + 1) * 32 + lane]);

    for (int n = 0; n < 32; n++) {
        int gn = nodeBase + n;
        if (gn >= NN) break;
        if (myct >= 0 && ct_s[n] != myct) continue;
        ull acc = 0ull;
        const ull* row = (const ull*)&srcm[n][0];
#pragma unroll
        for (int i = 0; i < 16; i++)
            fma2(acc, row[i], m2[i]);
        float2 f = unpack2(acc);
        outp[gn * OUTD + h * 32 + lane] = f.x + f.y;
    }
}

// ---------------- CSR build ----------------
__global__ void zero_kernel() {
    int stride = gridDim.x * blockDim.x;
    for (int i = blockIdx.x * blockDim.x + threadIdx.x; i < 3 * NN; i += stride)
        g_cnt[i] = 0;
    float2 z2 = make_float2(0.f, 0.f);
    for (int i = blockIdx.x * blockDim.x + threadIdx.x; i < 3 * NN * NH; i += stride)
        g_S[i] = z2;
}

__global__ void hist_kernel(const int* __restrict__ dst) {
    int stride = gridDim.x * blockDim.x;
    for (int i = blockIdx.x * blockDim.x + threadIdx.x; i < 3 * EE; i += stride) {
        int e = i / EE;
        int d = dst[i];
        atomicAdd(&g_cnt[e * NN + d], 1);
    }
}

__global__ void __launch_bounds__(1024) scan_kernel() {
    int e = blockIdx.x;
    int tid = threadIdx.x;
    int lane = tid & 31, wid = tid >> 5;
    __shared__ int wsum[32];
    int carry = 0;

    for (int chunk = 0; chunk < NN; chunk += 1024) {
        int i = chunk + tid;
        int v = (i < NN) ? g_cnt[e * NN + i] : 0;
        int x = v;
#pragma unroll
        for (int sh = 1; sh < 32; sh <<= 1) {
            int y = __shfl_up_sync(0xffffffffu, x, sh);
            if (lane >= sh) x += y;
        }
        if (lane == 31) wsum[wid] = x;
        __syncthreads();
        if (wid == 0) {
            int t2 = wsum[lane];
#pragma unroll
            for (int sh = 1; sh < 32; sh <<= 1) {
                int y = __shfl_up_sync(0xffffffffu, t2, sh);
                if (lane >= sh) t2 += y;
            }
            wsum[lane] = t2;
        }
        __syncthreads();
        int incl = x + (wid ? wsum[wid - 1] : 0);
        int excl = incl - v + carry;
        if (i < NN) {
            g_ptr[e * (NN + 1) + i] = excl;
            g_cur[e * NN + i] = excl;
        }
        carry += wsum[31];
        __syncthreads();
    }
    if (tid == 0) g_ptr[e * (NN + 1) + NN] = carry;
}

// ---------------- kernel 3: edge logits -> CSR-ordered exp records ----------------
// One warp per edge (edge-parallel: every edge independent, latency fully hidden).
// Claims a CSR slot via one atomic, writes (src, 8x(ea,eca)) in CSR order and
// red-accumulates softmax denominators. No segment-max: logits O(1), exp safe.
__global__ void __launch_bounds__(256) logits_kernel(
    const int* __restrict__ src, const int* __restrict__ dst,
    const float* __restrict__ pri, const float* __restrict__ pri_cau)
{
    int e = blockIdx.y;
    int edge = blockIdx.x * 8 + (threadIdx.x >> 5);
    if (edge >= EE) return;
    int lane = threadIdx.x & 31;
    int s = src[e * EE + edge];
    int d = dst[e * EE + edge];
    int off = lane * 4;

    const float* qp = g_Q + d * OUTD;
    const float* kp = g_K + s * OUTD;
    const float* mp = g_MK + s * OUTD;
    float4 qa = *(const float4*)(qp + off);
    float4 qb = *(const float4*)(qp + 128 + off);
    float4 ka = *(const float4*)(kp + off);
    float4 kb = *(const float4*)(kp + 128 + off);
    float4 ma = *(const float4*)(mp + off);
    float4 mb = *(const float4*)(mp + 128 + off);

    float p0 = dot4(qa, ka);
    float p1 = dot4(qb, kb);
    float m0 = dot4(qa, ma);
    float m1 = dot4(qb, mb);

#pragma unroll
    for (int sh = 1; sh <= 4; sh <<= 1) {
        p0 += __shfl_xor_sync(0xffffffffu, p0, sh);
        p1 += __shfl_xor_sync(0xffffffffu, p1, sh);
        m0 += __shfl_xor_sync(0xffffffffu, m0, sh);
        m1 += __shfl_xor_sync(0xffffffffu, m1, sh);
    }
    int g = lane >> 3;
    const float isdk = 0.17677669529663687f;  // 1/sqrt(32)
    float ea0 = __expf(p0 * pri[e * NH + g] * isdk);
    float ea1 = __expf(p1 * pri[e * NH + g + 4] * isdk);
    float ec0 = __expf(m0 * pri_cau[e * NH + g] * isdk);
    float ec1 = __expf(m1 * pri_cau[e * NH + g + 4] * isdk);

    // CSR slot for this edge (one atomic, broadcast)
    int pos = 0;
    if (lane == 0) pos = atomicAdd(&g_cur[e * NN + d], 1);
    pos = __shfl_sync(0xffffffffu, pos, 0);

    // redistribute so lane h (0..7) holds head h's (ea, eca)
    int srcl = (lane & 3) * 8;
    float va0 = __shfl_sync(0xffffffffu, ea0, srcl);
    float va1 = __shfl_sync(0xffffffffu, ea1, srcl);
    float vc0 = __shfl_sync(0xffffffffu, ec0, srcl);
    float vc1 = __shfl_sync(0xffffffffu, ec1, srcl);

    if (lane == 0) g_esrc[e * EE + pos] = s;
    if (lane < NH) {
        float ea = (lane < 4) ? va0 : va1;
        float ec = (lane < 4) ? vc0 : vc1;
        g_E[(e * EE + pos) * NH + lane] = make_float2(ea, ec);
        red_add_v2(&g_S[(e * NN + d) * NH + lane], ea, ec);
    }
}

// ---------------- kernel 4: CSR aggregation, warp-per-(dst, etype) ----------------
// Block = 96 threads = 3 warps; warp w handles etype w of node blockIdx.x.
// No shuffles / no exp in the loop: contiguous CSR records + val/cval gathers,
// register accumulation, smem combine, single float4 store. No output atomics.
__global__ void __launch_bounds__(96) csr_aggregate_kernel(
    const float* __restrict__ comb_pri, float* __restrict__ out)
{
    __shared__ float sh[3][OUTD];

    int d = blockIdx.x;
    int w = threadIdx.x >> 5;      // etype
    int lane = threadIdx.x & 31;
    int off = lane * 4;
    int g = lane >> 3;

    int beg = g_ptr[w * (NN + 1) + d];
    int end = g_ptr[w * (NN + 1) + d + 1];

    float4 ra = make_float4(0.f, 0.f, 0.f, 0.f);
    float4 rb = make_float4(0.f, 0.f, 0.f, 0.f);

    if (beg < end) {
        float2 S0 = g_S[(w * NN + d) * NH + g];
        float2 S1 = g_S[(w * NN + d) * NH + g + 4];
        float isa0 = __fdividef(1.f, S0.x);
        float isc0 = __fdividef(1.f, S0.y);
        float isa1 = __fdividef(1.f, S1.x);
        float isc1 = __fdividef(1.f, S1.y);

        const int* sl = g_esrc + w * EE;
        const float2* el = g_E + (long long)w * EE * NH;
        const float* valb = g_VAL + w * NN * OUTD;
        const float* cvalb = g_CVAL + w * NN * OUTD;

        float4 aa = make_float4(0.f, 0.f, 0.f, 0.f);
        float4 ab = make_float4(0.f, 0.f, 0.f, 0.f);
        float4 ca = make_float4(0.f, 0.f, 0.f, 0.f);
        float4 cb = make_float4(0.f, 0.f, 0.f, 0.f);

#pragma unroll 2
        for (int i = beg; i < end; i++) {
            int s = sl[i];
            float2 e0 = el[i * NH + g];
            float2 e1 = el[i * NH + g + 4];
            const float* vp = valb + s * OUTD;
            const float* cp = cvalb + s * OUTD;
            float4 v0 = *(const float4*)(vp + off);
            float4 v1 = *(const float4*)(vp + 128 + off);
            float4 c0 = *(const float4*)(cp + off);
            float4 c1 = *(const float4*)(cp + 128 + off);

            aa.x += e0.x * v0.x; aa.y += e0.x * v0.y; aa.z += e0.x * v0.z; aa.w += e0.x * v0.w;
            ab.x += e1.x * v1.x; ab.y += e1.x * v1.y; ab.z += e1.x * v1.z; ab.w += e1.x * v1.w;
            ca.x += e0.y * c0.x; ca.y += e0.y * c0.y; ca.z += e0.y * c0.z; ca.w += e0.y * c0.w;
            cb.x += e1.y * c1.x; cb.y += e1.y * c1.y; cb.z += e1.y * c1.z; cb.w += e1.y * c1.w;
        }

        float4 b0 = *(const float4*)&comb_pri[w * OUTD + off];
        float4 b1 = *(const float4*)&comb_pri[w * OUTD + 128 + off];
        ra.x = aa.x * isa0 + ca.x * isc0 * b0.x;
        ra.y = aa.y * isa0 + ca.y * isc0 * b0.y;
        ra.z = aa.z * isa0 + ca.z * isc0 * b0.z;
        ra.w = aa.w * isa0 + ca.w * isc0 * b0.w;
        rb.x = ab.x * isa1 + cb.x * isc1 * b1.x;
        rb.y = ab.y * isa1 + cb.y * isc1 * b1.y;
        rb.z = ab.z * isa1 + cb.z * isc1 * b1.z;
        rb.w = ab.w * isa1 + cb.w * isc1 * b1.w;
    }

    *(float4*)&sh[w][off] = ra;
    *(float4*)&sh[w][128 + off] = rb;
    __syncthreads();

    if (w == 0) {
        const float third = 1.0f / 3.0f;
        float4 s0a = *(float4*)&sh[0][off];
        float4 s1a = *(float4*)&sh[1][off];
        float4 s2a = *(float4*)&sh[2][off];
        float4 s0b = *(float4*)&sh[0][128 + off];
        float4 s1b = *(float4*)&sh[1][128 + off];
        float4 s2b = *(float4*)&sh[2][128 + off];
        float4 oa = make_float4(
            fmaxf((s0a.x + s1a.x + s2a.x) * third, 0.f),
            fmaxf((s0a.y + s1a.y + s2a.y) * third, 0.f),
            fmaxf((s0a.z + s1a.z + s2a.z) * third, 0.f),
            fmaxf((s0a.w + s1a.w + s2a.w) * third, 0.f));
        float4 ob = make_float4(
            fmaxf((s0b.x + s1b.x + s2b.x) * third, 0.f),
            fmaxf((s0b.y + s1b.y + s2b.y) * third, 0.f),
            fmaxf((s0b.z + s1b.z + s2b.z) * third, 0.f),
            fmaxf((s0b.w + s1b.w + s2b.w) * third, 0.f));
        *(float4*)(out + d * OUTD + off) = oa;
        *(float4*)(out + d * OUTD + 128 + off) = ob;
    }
}

// ---------------- launch ----------------
extern "C" void kernel_launch(void* const* d_in, const int* in_sizes, int n_in,
                              void* d_out, int out_size) {
    const float* x          = (const float*)d_in[0];
    const float* Wk         = (const float*)d_in[1];
    const float* bk         = (const float*)d_in[2];
    const float* Wq         = (const float*)d_in[3];
    const float* bq         = (const float*)d_in[4];
    const float* Wv         = (const float*)d_in[5];
    const float* bv         = (const float*)d_in[6];
    const float* pri        = (const float*)d_in[7];
    const float* msg        = (const float*)d_in[8];
    const float* pri_cau    = (const float*)d_in[9];
    const float* msg_cau    = (const float*)d_in[10];
    const float* comb_pri   = (const float*)d_in[11];
    const float* cau_filter = (const float*)d_in[12];
    const float* time_emb   = (const float*)d_in[13];
    const int*   cau_type   = (const int*)d_in[14];
    const int*   src        = (const int*)d_in[15];
    const int*   dst        = (const int*)d_in[16];
    float* out = (float*)d_out;

    // CSR prefix (independent of gemm/transform)
    zero_kernel<<<512, 256>>>();
    hist_kernel<<<512, 256>>>(dst);
    scan_kernel<<<3, 1024>>>();

    dim3 ggrid(768 / BN, (NN + BM - 1) / BM);
    gemm_qkv<<<ggrid, 256>>>(x, Wk, bk, Wq, bq, Wv, bv);

    dim3 tgrid((NN + 31) / 32, NH);
    transform_kernel<<<tgrid, 288>>>(msg, msg_cau, cau_filter, time_emb, cau_type);

    dim3 egrid((EE + 7) / 8, 3);
    logits_kernel<<<egrid, 256>>>(src, dst, pri, pri_cau);

    csr_aggregate_kernel<<<NN, 96>>>(comb_pri, out);
}

// round 8
// speedup vs baseline: 1.2899x; 1.2458x over previous
#include <cuda_runtime.h>
#include <cuda_bf16.h>
#include <math.h>
#include <stdint.h>

#define NN 20000
#define EE 160000
#define OUTD 256
#define INDIM 256
#define NH 8

typedef unsigned long long ull;

// ---------------- scratch (device globals; no allocation allowed) ----------------
__device__ float g_K[NN * OUTD];
__device__ float g_Q[NN * OUTD];
__device__ float g_V[NN * OUTD];
__device__ float g_MK[NN * OUTD];
__device__ float g_VAL[3 * NN * OUTD];
__device__ float g_CVAL[3 * NN * OUTD];
__device__ float2 g_E[3 * EE * NH];      // (ea, eca) per edge-head
__device__ float2 g_S[3 * NN * NH];      // (sum_ea, sum_eca) per dst-head
// bf16 hi/lo splits for tensor-core GEMM
__device__ __nv_bfloat16 g_xhi[NN * INDIM];
__device__ __nv_bfloat16 g_xlo[NN * INDIM];
__device__ __nv_bfloat16 g_wthi[768 * INDIM];   // [out_col][k] transposed
__device__ __nv_bfloat16 g_wtlo[768 * INDIM];

// ---------------- helpers ----------------
__device__ __forceinline__ ull pack2(float a, float b) {
    ull r; asm("mov.b64 %0, {%1, %2};" : "=l"(r) : "f"(a), "f"(b)); return r;
}
__device__ __forceinline__ void fma2(ull& acc, ull a, ull b) {
    asm("fma.rn.f32x2 %0, %1, %2, %0;" : "+l"(acc) : "l"(a), "l"(b));
}
__device__ __forceinline__ float2 unpack2(ull v) {
    float2 f; asm("mov.b64 {%0, %1}, %2;" : "=f"(f.x), "=f"(f.y) : "l"(v)); return f;
}
__device__ __forceinline__ float dot4(float4 a, float4 b) {
    return a.x * b.x + a.y * b.y + a.z * b.z + a.w * b.w;
}
__device__ __forceinline__ void red_add_v4(float* p, float a, float b, float c, float d) {
    asm volatile("red.global.add.v4.f32 [%0], {%1,%2,%3,%4};"
                 :: "l"(p), "f"(a), "f"(b), "f"(c), "f"(d) : "memory");
}
__device__ __forceinline__ void red_add_v2(float2* p, float a, float b) {
    asm volatile("red.global.add.v2.f32 [%0], {%1,%2};"
                 :: "l"(p), "f"(a), "f"(b) : "memory");
}
__device__ __forceinline__ uint32_t smem_to_u32(const void* p) {
    uint32_t a;
    asm("{ .reg .u64 t; cvta.to.shared.u64 t, %1; cvt.u32.u64 %0, t; }" : "=r"(a) : "l"(p));
    return a;
}
__device__ __forceinline__ void ldsm_x4(uint32_t* r, uint32_t addr) {
    asm volatile("ldmatrix.sync.aligned.m8n8.x4.shared.b16 {%0,%1,%2,%3}, [%4];"
        : "=r"(r[0]), "=r"(r[1]), "=r"(r[2]), "=r"(r[3]) : "r"(addr));
}
__device__ __forceinline__ void ldsm_x2(uint32_t* r, uint32_t addr) {
    asm volatile("ldmatrix.sync.aligned.m8n8.x2.shared.b16 {%0,%1}, [%2];"
        : "=r"(r[0]), "=r"(r[1]) : "r"(addr));
}
__device__ __forceinline__ void mma_bf16(float* c, const uint32_t* a, const uint32_t* b) {
    asm volatile("mma.sync.aligned.m16n8k16.row.col.f32.bf16.bf16.f32 "
        "{%0,%1,%2,%3}, {%4,%5,%6,%7}, {%8,%9}, {%0,%1,%2,%3};"
        : "+f"(c[0]), "+f"(c[1]), "+f"(c[2]), "+f"(c[3])
        : "r"(a[0]), "r"(a[1]), "r"(a[2]), "r"(a[3]), "r"(b[0]), "r"(b[1]));
}

// ---------------- kernel 0: zero accumulators ----------------
__global__ void zero_kernel(float* __restrict__ out) {
    int stride = gridDim.x * blockDim.x;
    for (int i = blockIdx.x * blockDim.x + threadIdx.x; i < NN * OUTD; i += stride)
        out[i] = 0.0f;
    float2 z2 = make_float2(0.f, 0.f);
    for (int i = blockIdx.x * blockDim.x + threadIdx.x; i < 3 * NN * NH; i += stride)
        g_S[i] = z2;
}

// ---------------- prep: fp32 -> bf16 hi/lo splits ----------------
__global__ void split_x_kernel(const float* __restrict__ x) {
    int i = blockIdx.x * blockDim.x + threadIdx.x;   // one float4 per thread
    if (i >= NN * INDIM / 4) return;
    float4 v = ((const float4*)x)[i];
    __nv_bfloat16 h[4], l[4];
    float f[4] = {v.x, v.y, v.z, v.w};
#pragma unroll
    for (int j = 0; j < 4; j++) {
        h[j] = __float2bfloat16(f[j]);
        l[j] = __float2bfloat16(f[j] - __bfloat162float(h[j]));
    }
    ((uint2*)g_xhi)[i] = *(uint2*)h;
    ((uint2*)g_xlo)[i] = *(uint2*)l;
}

// transpose + split W: g_wt[c][k] = W_sel[k][c%256]
__global__ void split_w_kernel(const float* __restrict__ Wk,
                               const float* __restrict__ Wq,
                               const float* __restrict__ Wv) {
    int i = blockIdx.x * blockDim.x + threadIdx.x;   // i = c*256 + k
    if (i >= 768 * INDIM) return;
    int c = i >> 8, k = i & 255;
    const float* W = (c < 256) ? Wk : ((c < 512) ? Wq : Wv);
    float v = W[k * 256 + (c & 255)];
    __nv_bfloat16 h = __float2bfloat16(v);
    __nv_bfloat16 l = __float2bfloat16(v - __bfloat162float(h));
    g_wthi[i] = h;
    g_wtlo[i] = l;
}

// ---------------- kernel 1: QKV GEMM via mma.sync bf16x3 ----------------
// Block 128x64, 8 warps (2x4), warp tile 64x16, K-chunk 32 (8 chunks).
// D = Ahi*Bhi + Ahi*Blo + Alo*Bhi accumulated in fp32.
__global__ void __launch_bounds__(256) gemm_mma(
    const float* __restrict__ bk, const float* __restrict__ bq, const float* __restrict__ bv)
{
    __shared__ __align__(16) unsigned char sm[30720];
    const int AHI = 0, ALO = 10240, BHI = 20480, BLO = 25600;

    int tid = threadIdx.x;
    int lane = tid & 31, wid = tid >> 5;
    int warp_m = wid >> 2, warp_n = wid & 3;
    int mbase = blockIdx.y * 128;
    int nbg = blockIdx.x * 64;       // global col base in 0..767

    uint32_t sb = smem_to_u32(sm);

    float acc[2][4][4];
#pragma unroll
    for (int nt = 0; nt < 2; nt++)
#pragma unroll
        for (int mt = 0; mt < 4; mt++)
#pragma unroll
            for (int j = 0; j < 4; j++) acc[nt][mt][j] = 0.0f;

    int arow = tid >> 1;            // 0..127
    int ahalf = (tid & 1) * 32;     // byte offset within 64B row
    int brow = tid & 63;            // 0..63
    int bsel = tid >> 6;            // 0..3 : {Bhi h0, Bhi h1, Blo h0, Blo h1}
    int bhalf = (bsel & 1) * 32;

    for (int chunk = 0; chunk < 8; chunk++) {
        int k0 = chunk * 32;
        // A tile (hi + lo): 128 rows x 32 bf16
        {
            int gn = mbase + arow;
            uint4 h0 = make_uint4(0,0,0,0), h1 = make_uint4(0,0,0,0);
            uint4 l0 = make_uint4(0,0,0,0), l1 = make_uint4(0,0,0,0);
            if (gn < NN) {
                const uint4* ph = (const uint4*)((const unsigned char*)(g_xhi + (size_t)gn * INDIM + k0) + ahalf);
                const uint4* pl = (const uint4*)((const unsigned char*)(g_xlo + (size_t)gn * INDIM + k0) + ahalf);
                h0 = ph[0]; h1 = ph[1];
                l0 = pl[0]; l1 = pl[1];
            }
            uint4* dh = (uint4*)(sm + AHI + arow * 80 + ahalf);
            uint4* dl = (uint4*)(sm + ALO + arow * 80 + ahalf);
            dh[0] = h0; dh[1] = h1;
            dl[0] = l0; dl[1] = l1;
        }
        // B tile (hi + lo): 64 rows x 32 bf16
        {
            const __nv_bfloat16* srcb = (bsel < 2) ? g_wthi : g_wtlo;
            const uint4* pb = (const uint4*)((const unsigned char*)(srcb + (size_t)(nbg + brow) * INDIM + k0) + bhalf);
            uint4* db = (uint4*)(sm + ((bsel < 2) ? BHI : BLO) + brow * 80 + bhalf);
            db[0] = pb[0]; db[1] = pb[1];
        }
        __syncthreads();

#pragma unroll
        for (int ks = 0; ks < 2; ks++) {
            uint32_t ah[4][4], al[4][4], bh[2][2], bl[2][2];
            int aoff = ks * 32 + ((lane >> 4) & 1) * 16;
#pragma unroll
            for (int mt = 0; mt < 4; mt++) {
                uint32_t addr = sb + AHI + (uint32_t)((warp_m * 64 + mt * 16 + (lane & 15)) * 80) + aoff;
                ldsm_x4(ah[mt], addr);
                ldsm_x4(al[mt], addr + (ALO - AHI));
            }
            int boff = ks * 32 + ((lane >> 3) & 1) * 16;
#pragma unroll
            for (int nt = 0; nt < 2; nt++) {
                uint32_t baddr = sb + BHI + (uint32_t)((warp_n * 16 + nt * 8 + (lane & 7)) * 80) + boff;
                ldsm_x2(bh[nt], baddr);
                ldsm_x2(bl[nt], baddr + (BLO - BHI));
            }
#pragma unroll
            for (int mt = 0; mt < 4; mt++)
#pragma unroll
                for (int nt = 0; nt < 2; nt++) {
                    mma_bf16(acc[nt][mt], ah[mt], bh[nt]);
                    mma_bf16(acc[nt][mt], ah[mt], bl[nt]);
                    mma_bf16(acc[nt][mt], al[mt], bh[nt]);
                }
        }
        __syncthreads();
    }

    // epilogue: direct float2 stores + bias
    int buf = nbg >> 8;
    int col0 = nbg & 255;
    float* outp = (buf == 0) ? g_K : ((buf == 1) ? g_Q : g_V);
    const float* bias = (buf == 0) ? bk : ((buf == 1) ? bq : bv);

#pragma unroll
    for (int mt = 0; mt < 4; mt++) {
        int r0 = mbase + warp_m * 64 + mt * 16 + (lane >> 2);
#pragma unroll
        for (int nt = 0; nt < 2; nt++) {
            int c = col0 + warp_n * 16 + nt * 8 + (lane & 3) * 2;
            float2 bb = *(const float2*)&bias[c];
            if (r0 < NN) {
                float2 o = make_float2(acc[nt][mt][0] + bb.x, acc[nt][mt][1] + bb.y);
                *(float2*)&outp[(size_t)r0 * OUTD + c] = o;
            }
            if (r0 + 8 < NN) {
                float2 o = make_float2(acc[nt][mt][2] + bb.x, acc[nt][mt][3] + bb.y);
                *(float2*)&outp[(size_t)(r0 + 8) * OUTD + c] = o;
            }
        }
    }
}

// ---------------- kernel 2: node-level relation transforms ----------------
__global__ void __launch_bounds__(288) transform_kernel(
    const float* __restrict__ msg, const float* __restrict__ msg_cau,
    const float* __restrict__ cau_filter, const float* __restrict__ time_emb,
    const int* __restrict__ cau_type)
{
    __shared__ float k_s[32][32];
    __shared__ float v_s[32][32];
    __shared__ float vt_s[32][32];
    __shared__ int ct_s[32];

    int h = blockIdx.y;
    int nodeBase = blockIdx.x * 32;
    int tid = threadIdx.x;

    for (int idx = tid; idx < 32 * 32; idx += 288) {
        int n = idx >> 5, dcol = idx & 31;
        int gn = nodeBase + n;
        float kv = 0.f, vv = 0.f;
        if (gn < NN) {
            kv = g_K[gn * OUTD + h * 32 + dcol];
            vv = g_V[gn * OUTD + h * 32 + dcol];
        }
        k_s[n][dcol] = kv;
        v_s[n][dcol] = vv;
        vt_s[n][dcol] = vv + time_emb[h * 32 + dcol];
    }
    for (int idx = tid; idx < 32; idx += 288) {
        int gn = nodeBase + idx;
        ct_s[idx] = (gn < NN) ? cau_type[gn] : -1;
    }
    __syncthreads();

    int wid = tid >> 5, lane = tid & 31;
    const float* mat;
    const float (*srcm)[32];
    float* outp;
    int myct = -1;
    if (wid < 3) {
        mat = cau_filter + (wid * NH + h) * 1024;
        srcm = k_s; outp = g_MK; myct = wid;
    } else if (wid < 6) {
        int e = wid - 3;
        mat = msg + (e * NH + h) * 1024;
        srcm = v_s; outp = g_VAL + e * NN * OUTD;
    } else {
        int e = wid - 6;
        mat = msg_cau + (e * NH + h) * 1024;
        srcm = vt_s; outp = g_CVAL + e * NN * OUTD;
    }

    ull m2[16];
#pragma unroll
    for (int i = 0; i < 16; i++)
        m2[i] = pack2(mat[(2 * i) * 32 + lane], mat[(2 * i + 1) * 32 + lane]);

    for (int n = 0; n < 32; n++) {
        int gn = nodeBase + n;
        if (gn >= NN) break;
        if (myct >= 0 && ct_s[n] != myct) continue;
        ull acc = 0ull;
        const ull* row = (const ull*)&srcm[n][0];
#pragma unroll
        for (int i = 0; i < 16; i++)
            fma2(acc, row[i], m2[i]);
        float2 f = unpack2(acc);
        outp[gn * OUTD + h * 32 + lane] = f.x + f.y;
    }
}

// ---------------- kernel 3: edge logits + softmax denominators ----------------
__global__ void __launch_bounds__(256) logits_kernel(
    const int* __restrict__ src, const int* __restrict__ dst,
    const float* __restrict__ pri, const float* __restrict__ pri_cau)
{
    int e = blockIdx.y;
    int edge = blockIdx.x * 8 + (threadIdx.x >> 5);
    if (edge >= EE) return;
    int lane = threadIdx.x & 31;
    int s = src[e * EE + edge];
    int d = dst[e * EE + edge];
    int off = lane * 4;

    const float* qp = g_Q + d * OUTD;
    const float* kp = g_K + s * OUTD;
    const float* mp = g_MK + s * OUTD;
    float4 qa = *(const float4*)(qp + off);
    float4 qb = *(const float4*)(qp + 128 + off);
    float4 ka = *(const float4*)(kp + off);
    float4 kb = *(const float4*)(kp + 128 + off);
    float4 ma = *(const float4*)(mp + off);
    float4 mb = *(const float4*)(mp + 128 + off);

    float p0 = dot4(qa, ka);
    float p1 = dot4(qb, kb);
    float m0 = dot4(qa, ma);
    float m1 = dot4(qb, mb);

#pragma unroll
    for (int sh = 1; sh <= 4; sh <<= 1) {
        p0 += __shfl_xor_sync(0xffffffffu, p0, sh);
        p1 += __shfl_xor_sync(0xffffffffu, p1, sh);
        m0 += __shfl_xor_sync(0xffffffffu, m0, sh);
        m1 += __shfl_xor_sync(0xffffffffu, m1, sh);
    }
    int g = lane >> 3;
    const float isdk = 0.17677669529663687f;  // 1/sqrt(32)
    float ea0 = __expf(p0 * pri[e * NH + g] * isdk);
    float ea1 = __expf(p1 * pri[e * NH + g + 4] * isdk);
    float ec0 = __expf(m0 * pri_cau[e * NH + g] * isdk);
    float ec1 = __expf(m1 * pri_cau[e * NH + g + 4] * isdk);

    int srcl = (lane & 3) * 8;
    float va0 = __shfl_sync(0xffffffffu, ea0, srcl);
    float va1 = __shfl_sync(0xffffffffu, ea1, srcl);
    float vc0 = __shfl_sync(0xffffffffu, ec0, srcl);
    float vc1 = __shfl_sync(0xffffffffu, ec1, srcl);

    if (lane < NH) {
        float ea = (lane < 4) ? va0 : va1;
        float ec = (lane < 4) ? vc0 : vc1;
        int eidx = e * EE + edge;
        g_E[eidx * NH + lane] = make_float2(ea, ec);
        red_add_v2(&g_S[(e * NN + d) * NH + lane], ea, ec);
    }
}

// ---------------- kernel 4: weighted aggregation ----------------
__global__ void __launch_bounds__(256) aggregate_kernel(
    const int* __restrict__ src, const int* __restrict__ dst,
    const float* __restrict__ comb_pri, float* __restrict__ out)
{
    int e = blockIdx.y;
    int edge = blockIdx.x * 8 + (threadIdx.x >> 5);
    if (edge >= EE) return;
    int lane = threadIdx.x & 31;
    int s = src[e * EE + edge];
    int d = dst[e * EE + edge];
    int h0 = lane >> 3;
    int h1 = h0 + 4;
    int eidx = e * EE + edge;

    float2 eh0 = g_E[eidx * NH + h0];
    float2 eh1 = g_E[eidx * NH + h1];
    float2 s0 = g_S[(e * NN + d) * NH + h0];
    float2 s1 = g_S[(e * NN + d) * NH + h1];
    float wa0 = __fdividef(eh0.x, s0.x);
    float wc0 = __fdividef(eh0.y, s0.y);
    float wa1 = __fdividef(eh1.x, s1.x);
    float wc1 = __fdividef(eh1.y, s1.y);

    int off = lane * 4;
    const float* vp = g_VAL  + e * NN * OUTD + s * OUTD;
    const float* cp = g_CVAL + e * NN * OUTD + s * OUTD;
    float4 v0 = *(const float4*)(vp + off);
    float4 v1 = *(const float4*)(vp + 128 + off);
    float4 c0 = *(const float4*)(cp + off);
    float4 c1 = *(const float4*)(cp + 128 + off);
    float4 b0 = *(const float4*)&comb_pri[e * OUTD + off];
    float4 b1 = *(const float4*)&comb_pri[e * OUTD + 128 + off];

    float r0 = wa0 * v0.x + wc0 * b0.x * c0.x;
    float r1 = wa0 * v0.y + wc0 * b0.y * c0.y;
    float r2 = wa0 * v0.z + wc0 * b0.z * c0.z;
    float r3 = wa0 * v0.w + wc0 * b0.w * c0.w;
    float r4 = wa1 * v1.x + wc1 * b1.x * c1.x;
    float r5 = wa1 * v1.y + wc1 * b1.y * c1.y;
    float r6 = wa1 * v1.z + wc1 * b1.z * c1.z;
    float r7 = wa1 * v1.w + wc1 * b1.w * c1.w;

    float* op = out + d * OUTD;
    red_add_v4(op + off, r0, r1, r2, r3);
    red_add_v4(op + 128 + off, r4, r5, r6, r7);
}

// ---------------- kernel 5: finalize (mean over 3 etypes + relu) ----------------
__global__ void finalize_kernel(float* __restrict__ out) {
    int i = blockIdx.x * blockDim.x + threadIdx.x;
    if (i < NN * OUTD) {
        float v = out[i] * (1.0f / 3.0f);
        out[i] = v > 0.0f ? v : 0.0f;
    }
}

// ---------------- launch ----------------
extern "C" void kernel_launch(void* const* d_in, const int* in_sizes, int n_in,
                              void* d_out, int out_size) {
    const float* x          = (const float*)d_in[0];
    const float* Wk         = (const float*)d_in[1];
    const float* bk         = (const float*)d_in[2];
    const float* Wq         = (const float*)d_in[3];
    const float* bq         = (const float*)d_in[4];
    const float* Wv         = (const float*)d_in[5];
    const float* bv         = (const float*)d_in[6];
    const float* pri        = (const float*)d_in[7];
    const float* msg        = (const float*)d_in[8];
    const float* pri_cau    = (const float*)d_in[9];
    const float* msg_cau    = (const float*)d_in[10];
    const float* comb_pri   = (const float*)d_in[11];
    const float* cau_filter = (const float*)d_in[12];
    const float* time_emb   = (const float*)d_in[13];
    const int*   cau_type   = (const int*)d_in[14];
    const int*   src        = (const int*)d_in[15];
    const int*   dst        = (const int*)d_in[16];
    float* out = (float*)d_out;

    zero_kernel<<<2048, 256>>>(out);

    split_x_kernel<<<(NN * INDIM / 4 + 255) / 256, 256>>>(x);
    split_w_kernel<<<768, 256>>>(Wk, Wq, Wv);

    gemm_mma<<<dim3(12, 157), 256>>>(bk, bq, bv);

    dim3 tgrid((NN + 31) / 32, NH);
    transform_kernel<<<tgrid, 288>>>(msg, msg_cau, cau_filter, time_emb, cau_type);

    dim3 egrid((EE + 7) / 8, 3);
    logits_kernel<<<egrid, 256>>>(src, dst, pri, pri_cau);
    aggregate_kernel<<<egrid, 256>>>(src, dst, comb_pri, out);

    finalize_kernel<<<(NN * OUTD + 255) / 256, 256>>>(out);
}

// round 9
// speedup vs baseline: 1.3889x; 1.0767x over previous
#include <cuda_runtime.h>
#include <cuda_bf16.h>
#include <math.h>
#include <stdint.h>

#define NN 20000
#define EE 160000
#define OUTD 256
#define INDIM 256
#define NH 8

typedef unsigned long long ull;

// ---------------- scratch (device globals; no allocation allowed) ----------------
__device__ float g_K[NN * OUTD];
__device__ float g_Q[NN * OUTD];
__device__ float g_V[NN * OUTD];
__device__ float g_MK[NN * OUTD];
__device__ float g_VAL[3 * NN * OUTD];
__device__ float g_CVAL[3 * NN * OUTD];
__device__ float2 g_E[3 * EE * NH];      // (ea, eca) per edge-head
__device__ float2 g_S[3 * NN * NH];      // (sum_ea, sum_eca) per dst-head
// bf16 hi/lo splits for tensor-core GEMM
__device__ __nv_bfloat16 g_xhi[NN * INDIM];
__device__ __nv_bfloat16 g_xlo[NN * INDIM];
__device__ __nv_bfloat16 g_wthi[768 * INDIM];   // [out_col][k] transposed
__device__ __nv_bfloat16 g_wtlo[768 * INDIM];

// ---------------- helpers ----------------
__device__ __forceinline__ ull pack2(float a, float b) {
    ull r; asm("mov.b64 %0, {%1, %2};" : "=l"(r) : "f"(a), "f"(b)); return r;
}
__device__ __forceinline__ void fma2(ull& acc, ull a, ull b) {
    asm("fma.rn.f32x2 %0, %1, %2, %0;" : "+l"(acc) : "l"(a), "l"(b));
}
__device__ __forceinline__ float2 unpack2(ull v) {
    float2 f; asm("mov.b64 {%0, %1}, %2;" : "=f"(f.x), "=f"(f.y) : "l"(v)); return f;
}
__device__ __forceinline__ float dot4(float4 a, float4 b) {
    return a.x * b.x + a.y * b.y + a.z * b.z + a.w * b.w;
}
__device__ __forceinline__ void red_add_v4(float* p, float a, float b, float c, float d) {
    asm volatile("red.global.add.v4.f32 [%0], {%1,%2,%3,%4};"
                 :: "l"(p), "f"(a), "f"(b), "f"(c), "f"(d) : "memory");
}
__device__ __forceinline__ void red_add_v2(float2* p, float a, float b) {
    asm volatile("red.global.add.v2.f32 [%0], {%1,%2};"
                 :: "l"(p), "f"(a), "f"(b) : "memory");
}
__device__ __forceinline__ uint32_t smem_to_u32(const void* p) {
    uint32_t a;
    asm("{ .reg .u64 t; cvta.to.shared.u64 t, %1; cvt.u32.u64 %0, t; }" : "=r"(a) : "l"(p));
    return a;
}
__device__ __forceinline__ void ldsm_x4(uint32_t* r, uint32_t addr) {
    asm volatile("ldmatrix.sync.aligned.m8n8.x4.shared.b16 {%0,%1,%2,%3}, [%4];"
        : "=r"(r[0]), "=r"(r[1]), "=r"(r[2]), "=r"(r[3]) : "r"(addr));
}
__device__ __forceinline__ void mma_bf16(float* c, const uint32_t* a, const uint32_t* b) {
    asm volatile("mma.sync.aligned.m16n8k16.row.col.f32.bf16.bf16.f32 "
        "{%0,%1,%2,%3}, {%4,%5,%6,%7}, {%8,%9}, {%0,%1,%2,%3};"
        : "+f"(c[0]), "+f"(c[1]), "+f"(c[2]), "+f"(c[3])
        : "r"(a[0]), "r"(a[1]), "r"(a[2]), "r"(a[3]), "r"(b[0]), "r"(b[1]));
}

// ---------------- kernel 0: zero accumulators ----------------
__global__ void zero_kernel(float* __restrict__ out) {
    int stride = gridDim.x * blockDim.x;
    for (int i = blockIdx.x * blockDim.x + threadIdx.x; i < NN * OUTD; i += stride)
        out[i] = 0.0f;
    float2 z2 = make_float2(0.f, 0.f);
    for (int i = blockIdx.x * blockDim.x + threadIdx.x; i < 3 * NN * NH; i += stride)
        g_S[i] = z2;
}

// ---------------- prep: fp32 -> bf16 hi/lo splits ----------------
__global__ void split_x_kernel(const float* __restrict__ x) {
    int i = blockIdx.x * blockDim.x + threadIdx.x;   // one float4 per thread
    if (i >= NN * INDIM / 4) return;
    float4 v = ((const float4*)x)[i];
    __nv_bfloat16 h[4], l[4];
    float f[4] = {v.x, v.y, v.z, v.w};
#pragma unroll
    for (int j = 0; j < 4; j++) {
        h[j] = __float2bfloat16(f[j]);
        l[j] = __float2bfloat16(f[j] - __bfloat162float(h[j]));
    }
    ((uint2*)g_xhi)[i] = *(uint2*)h;
    ((uint2*)g_xlo)[i] = *(uint2*)l;
}

// transpose + split W: g_wt[c][k] = W_sel[k][c%256]
__global__ void split_w_kernel(const float* __restrict__ Wk,
                               const float* __restrict__ Wq,
                               const float* __restrict__ Wv) {
    int i = blockIdx.x * blockDim.x + threadIdx.x;   // i = c*256 + k
    if (i >= 768 * INDIM) return;
    int c = i >> 8, k = i & 255;
    const float* W = (c < 256) ? Wk : ((c < 512) ? Wq : Wv);
    float v = W[k * 256 + (c & 255)];
    __nv_bfloat16 h = __float2bfloat16(v);
    __nv_bfloat16 l = __float2bfloat16(v - __bfloat162float(h));
    g_wthi[i] = h;
    g_wtlo[i] = l;
}

// ---------------- kernel 1: QKV GEMM via mma.sync bf16x3 ----------------
// Block tile 128x128, 8 warps (2m x 4n), warp tile 64x32, K-chunk 32 (8 chunks).
// B fragments loaded with ldmatrix.x4 (two n8 frags per instruction).
// D = Ahi*Bhi + Ahi*Blo + Alo*Bhi accumulated in fp32.
__global__ void __launch_bounds__(256, 2) gemm_mma(
    const float* __restrict__ bk, const float* __restrict__ bq, const float* __restrict__ bv)
{
    __shared__ __align__(16) unsigned char sm[40960];
    const int AHI = 0, ALO = 10240, BHI = 20480, BLO = 30720;

    int tid = threadIdx.x;
    int lane = tid & 31, wid = tid >> 5;
    int warp_m = wid >> 2;      // 0..1  (64-row slab)
    int warp_n = wid & 3;       // 0..3  (32-col slab)
    int mbase = blockIdx.y * 128;
    int nbg = blockIdx.x * 128;  // global col base in 0..767

    uint32_t sb = smem_to_u32(sm);

    float acc[4][4][4];          // [nt][mt][frag]
#pragma unroll
    for (int nt = 0; nt < 4; nt++)
#pragma unroll
        for (int mt = 0; mt < 4; mt++)
#pragma unroll
            for (int j = 0; j < 4; j++) acc[nt][mt][j] = 0.0f;

    int arow = tid >> 1;            // 0..127
    int ahalf = (tid & 1) * 32;     // byte offset within 64B row

    for (int chunk = 0; chunk < 8; chunk++) {
        int k0 = chunk * 32;
        // A tile (hi + lo): 128 rows x 32 bf16
        {
            int gn = mbase + arow;
            uint4 h0 = make_uint4(0,0,0,0), h1 = make_uint4(0,0,0,0);
            uint4 l0 = make_uint4(0,0,0,0), l1 = make_uint4(0,0,0,0);
            if (gn < NN) {
                const uint4* ph = (const uint4*)((const unsigned char*)(g_xhi + (size_t)gn * INDIM + k0) + ahalf);
                const uint4* pl = (const uint4*)((const unsigned char*)(g_xlo + (size_t)gn * INDIM + k0) + ahalf);
                h0 = ph[0]; h1 = ph[1];
                l0 = pl[0]; l1 = pl[1];
            }
            uint4* dh = (uint4*)(sm + AHI + arow * 80 + ahalf);
            uint4* dl = (uint4*)(sm + ALO + arow * 80 + ahalf);
            dh[0] = h0; dh[1] = h1;
            dl[0] = l0; dl[1] = l1;
        }
        // B tile (hi + lo): 128 rows x 32 bf16
        {
            const uint4* ph = (const uint4*)((const unsigned char*)(g_wthi + (size_t)(nbg + arow) * INDIM + k0) + ahalf);
            const uint4* pl = (const uint4*)((const unsigned char*)(g_wtlo + (size_t)(nbg + arow) * INDIM + k0) + ahalf);
            uint4* dh = (uint4*)(sm + BHI + arow * 80 + ahalf);
            uint4* dl = (uint4*)(sm + BLO + arow * 80 + ahalf);
            dh[0] = ph[0]; dh[1] = ph[1];
            dl[0] = pl[0]; dl[1] = pl[1];
        }
        __syncthreads();

#pragma unroll
        for (int ks = 0; ks < 2; ks++) {
            // B frags first: 2 x4 hi + 2 x4 lo cover all 4 n8 tiles of the 32-col slab
            uint32_t bh[2][4], bl[2][4];
            int boff = ks * 32 + ((lane >> 3) & 1) * 16;
#pragma unroll
            for (int np = 0; np < 2; np++) {
                int br = warp_n * 32 + np * 16 + ((lane >> 4) & 1) * 8 + (lane & 7);
                uint32_t baddr = sb + BHI + (uint32_t)(br * 80) + boff;
                ldsm_x4(bh[np], baddr);
                ldsm_x4(bl[np], baddr + (BLO - BHI));
            }
            int aoff = ks * 32 + ((lane >> 4) & 1) * 16;
#pragma unroll
            for (int mt = 0; mt < 4; mt++) {
                uint32_t ah[4], al[4];
                uint32_t addr = sb + AHI + (uint32_t)((warp_m * 64 + mt * 16 + (lane & 15)) * 80) + aoff;
                ldsm_x4(ah, addr);
                ldsm_x4(al, addr + (ALO - AHI));
#pragma unroll
                for (int np = 0; np < 2; np++)
#pragma unroll
                    for (int sub = 0; sub < 2; sub++) {
                        int nt = np * 2 + sub;
                        mma_bf16(acc[nt][mt], ah, &bh[np][sub * 2]);
                        mma_bf16(acc[nt][mt], ah, &bl[np][sub * 2]);
                        mma_bf16(acc[nt][mt], al, &bh[np][sub * 2]);
                    }
            }
        }
        __syncthreads();
    }

    // epilogue: direct float2 stores + bias (block's 128 cols stay in one buffer)
    int buf = nbg >> 8;
    int col0 = (nbg & 255) + warp_n * 32;
    float* outp = (buf == 0) ? g_K : ((buf == 1) ? g_Q : g_V);
    const float* bias = (buf == 0) ? bk : ((buf == 1) ? bq : bv);

#pragma unroll
    for (int mt = 0; mt < 4; mt++) {
        int r0 = mbase + warp_m * 64 + mt * 16 + (lane >> 2);
#pragma unroll
        for (int nt = 0; nt < 4; nt++) {
            int c = col0 + nt * 8 + (lane & 3) * 2;
            float2 bb = *(const float2*)&bias[c];
            if (r0 < NN) {
                float2 o = make_float2(acc[nt][mt][0] + bb.x, acc[nt][mt][1] + bb.y);
                *(float2*)&outp[(size_t)r0 * OUTD + c] = o;
            }
            if (r0 + 8 < NN) {
                float2 o = make_float2(acc[nt][mt][2] + bb.x, acc[nt][mt][3] + bb.y);
                *(float2*)&outp[(size_t)(r0 + 8) * OUTD + c] = o;
            }
        }
    }
}

// ---------------- kernel 2: node-level relation transforms ----------------
__global__ void __launch_bounds__(288) transform_kernel(
    const float* __restrict__ msg, const float* __restrict__ msg_cau,
    const float* __restrict__ cau_filter, const float* __restrict__ time_emb,
    const int* __restrict__ cau_type)
{
    __shared__ float k_s[32][32];
    __shared__ float v_s[32][32];
    __shared__ float vt_s[32][32];
    __shared__ int ct_s[32];

    int h = blockIdx.y;
    int nodeBase = blockIdx.x * 32;
    int tid = threadIdx.x;

    for (int idx = tid; idx < 32 * 32; idx += 288) {
        int n = idx >> 5, dcol = idx & 31;
        int gn = nodeBase + n;
        float kv = 0.f, vv = 0.f;
        if (gn < NN) {
            kv = g_K[gn * OUTD + h * 32 + dcol];
            vv = g_V[gn * OUTD + h * 32 + dcol];
        }
        k_s[n][dcol] = kv;
        v_s[n][dcol] = vv;
        vt_s[n][dcol] = vv + time_emb[h * 32 + dcol];
    }
    for (int idx = tid; idx < 32; idx += 288) {
        int gn = nodeBase + idx;
        ct_s[idx] = (gn < NN) ? cau_type[gn] : -1;
    }
    __syncthreads();

    int wid = tid >> 5, lane = tid & 31;
    const float* mat;
    const float (*srcm)[32];
    float* outp;
    int myct = -1;
    if (wid < 3) {
        mat = cau_filter + (wid * NH + h) * 1024;
        srcm = k_s; outp = g_MK; myct = wid;
    } else if (wid < 6) {
        int e = wid - 3;
        mat = msg + (e * NH + h) * 1024;
        srcm = v_s; outp = g_VAL + e * NN * OUTD;
    } else {
        int e = wid - 6;
        mat = msg_cau + (e * NH + h) * 1024;
        srcm = vt_s; outp = g_CVAL + e * NN * OUTD;
    }

    ull m2[16];
#pragma unroll
    for (int i = 0; i < 16; i++)
        m2[i] = pack2(mat[(2 * i) * 32 + lane], mat[(2 * i + 1) * 32 + lane]);

    for (int n = 0; n < 32; n++) {
        int gn = nodeBase + n;
        if (gn >= NN) break;
        if (myct >= 0 && ct_s[n] != myct) continue;
        ull acc = 0ull;
        const ull* row = (const ull*)&srcm[n][0];
#pragma unroll
        for (int i = 0; i < 16; i++)
            fma2(acc, row[i], m2[i]);
        float2 f = unpack2(acc);
        outp[gn * OUTD + h * 32 + lane] = f.x + f.y;
    }
}

// ---------------- kernel 3: edge logits + softmax denominators ----------------
__global__ void __launch_bounds__(256) logits_kernel(
    const int* __restrict__ src, const int* __restrict__ dst,
    const float* __restrict__ pri, const float* __restrict__ pri_cau)
{
    int e = blockIdx.y;
    int edge = blockIdx.x * 8 + (threadIdx.x >> 5);
    if (edge >= EE) return;
    int lane = threadIdx.x & 31;
    int s = src[e * EE + edge];
    int d = dst[e * EE + edge];
    int off = lane * 4;

    const float* qp = g_Q + d * OUTD;
    const float* kp = g_K + s * OUTD;
    const float* mp = g_MK + s * OUTD;
    float4 qa = *(const float4*)(qp + off);
    float4 qb = *(const float4*)(qp + 128 + off);
    float4 ka = *(const float4*)(kp + off);
    float4 kb = *(const float4*)(kp + 128 + off);
    float4 ma = *(const float4*)(mp + off);
    float4 mb = *(const float4*)(mp + 128 + off);

    float p0 = dot4(qa, ka);
    float p1 = dot4(qb, kb);
    float m0 = dot4(qa, ma);
    float m1 = dot4(qb, mb);

#pragma unroll
    for (int sh = 1; sh <= 4; sh <<= 1) {
        p0 += __shfl_xor_sync(0xffffffffu, p0, sh);
        p1 += __shfl_xor_sync(0xffffffffu, p1, sh);
        m0 += __shfl_xor_sync(0xffffffffu, m0, sh);
        m1 += __shfl_xor_sync(0xffffffffu, m1, sh);
    }
    int g = lane >> 3;
    const float isdk = 0.17677669529663687f;  // 1/sqrt(32)
    float ea0 = __expf(p0 * pri[e * NH + g] * isdk);
    float ea1 = __expf(p1 * pri[e * NH + g + 4] * isdk);
    float ec0 = __expf(m0 * pri_cau[e * NH + g] * isdk);
    float ec1 = __expf(m1 * pri_cau[e * NH + g + 4] * isdk);

    int srcl = (lane & 3) * 8;
    float va0 = __shfl_sync(0xffffffffu, ea0, srcl);
    float va1 = __shfl_sync(0xffffffffu, ea1, srcl);
    float vc0 = __shfl_sync(0xffffffffu, ec0, srcl);
    float vc1 = __shfl_sync(0xffffffffu, ec1, srcl);

    if (lane < NH) {
        float ea = (lane < 4) ? va0 : va1;
        float ec = (lane < 4) ? vc0 : vc1;
        int eidx = e * EE + edge;
        g_E[eidx * NH + lane] = make_float2(ea, ec);
        red_add_v2(&g_S[(e * NN + d) * NH + lane], ea, ec);
    }
}

// ---------------- kernel 4: weighted aggregation ----------------
__global__ void __launch_bounds__(256) aggregate_kernel(
    const int* __restrict__ src, const int* __restrict__ dst,
    const float* __restrict__ comb_pri, float* __restrict__ out)
{
    int e = blockIdx.y;
    int edge = blockIdx.x * 8 + (threadIdx.x >> 5);
    if (edge >= EE) return;
    int lane = threadIdx.x & 31;
    int s = src[e * EE + edge];
    int d = dst[e * EE + edge];
    int h0 = lane >> 3;
    int h1 = h0 + 4;
    int eidx = e * EE + edge;

    float2 eh0 = g_E[eidx * NH + h0];
    float2 eh1 = g_E[eidx * NH + h1];
    float2 s0 = g_S[(e * NN + d) * NH + h0];
    float2 s1 = g_S[(e * NN + d) * NH + h1];
    float wa0 = __fdividef(eh0.x, s0.x);
    float wc0 = __fdividef(eh0.y, s0.y);
    float wa1 = __fdividef(eh1.x, s1.x);
    float wc1 = __fdividef(eh1.y, s1.y);

    int off = lane * 4;
    const float* vp = g_VAL  + e * NN * OUTD + s * OUTD;
    const float* cp = g_CVAL + e * NN * OUTD + s * OUTD;
    float4 v0 = *(const float4*)(vp + off);
    float4 v1 = *(const float4*)(vp + 128 + off);
    float4 c0 = *(const float4*)(cp + off);
    float4 c1 = *(const float4*)(cp + 128 + off);
    float4 b0 = *(const float4*)&comb_pri[e * OUTD + off];
    float4 b1 = *(const float4*)&comb_pri[e * OUTD + 128 + off];

    float r0 = wa0 * v0.x + wc0 * b0.x * c0.x;
    float r1 = wa0 * v0.y + wc0 * b0.y * c0.y;
    float r2 = wa0 * v0.z + wc0 * b0.z * c0.z;
    float r3 = wa0 * v0.w + wc0 * b0.w * c0.w;
    float r4 = wa1 * v1.x + wc1 * b1.x * c1.x;
    float r5 = wa1 * v1.y + wc1 * b1.y * c1.y;
    float r6 = wa1 * v1.z + wc1 * b1.z * c1.z;
    float r7 = wa1 * v1.w + wc1 * b1.w * c1.w;

    float* op = out + d * OUTD;
    red_add_v4(op + off, r0, r1, r2, r3);
    red_add_v4(op + 128 + off, r4, r5, r6, r7);
}

// ---------------- kernel 5: finalize (mean over 3 etypes + relu) ----------------
__global__ void finalize_kernel(float* __restrict__ out) {
    int i = blockIdx.x * blockDim.x + threadIdx.x;
    if (i < NN * OUTD) {
        float v = out[i] * (1.0f / 3.0f);
        out[i] = v > 0.0f ? v : 0.0f;
    }
}

// ---------------- launch ----------------
extern "C" void kernel_launch(void* const* d_in, const int* in_sizes, int n_in,
                              void* d_out, int out_size) {
    const float* x          = (const float*)d_in[0];
    const float* Wk         = (const float*)d_in[1];
    const float* bk         = (const float*)d_in[2];
    const float* Wq         = (const float*)d_in[3];
    const float* bq         = (const float*)d_in[4];
    const float* Wv         = (const float*)d_in[5];
    const float* bv         = (const float*)d_in[6];
    const float* pri        = (const float*)d_in[7];
    const float* msg        = (const float*)d_in[8];
    const float* pri_cau    = (const float*)d_in[9];
    const float* msg_cau    = (const float*)d_in[10];
    const float* comb_pri   = (const float*)d_in[11];
    const float* cau_filter = (const float*)d_in[12];
    const float* time_emb   = (const float*)d_in[13];
    const int*   cau_type   = (const int*)d_in[14];
    const int*   src        = (const int*)d_in[15];
    const int*   dst        = (const int*)d_in[16];
    float* out = (float*)d_out;

    zero_kernel<<<2048, 256>>>(out);

    split_x_kernel<<<(NN * INDIM / 4 + 255) / 256, 256>>>(x);
    split_w_kernel<<<768, 256>>>(Wk, Wq, Wv);

    gemm_mma<<<dim3(6, 157), 256>>>(bk, bq, bv);

    dim3 tgrid((NN + 31) / 32, NH);
    transform_kernel<<<tgrid, 288>>>(msg, msg_cau, cau_filter, time_emb, cau_type);

    dim3 egrid((EE + 7) / 8, 3);
    logits_kernel<<<egrid, 256>>>(src, dst, pri, pri_cau);
    aggregate_kernel<<<egrid, 256>>>(src, dst, comb_pri, out);

    finalize_kernel<<<(NN * OUTD + 255) / 256, 256>>>(out);
}

// round 10
// speedup vs baseline: 1.4916x; 1.0740x over previous
#include <cuda_runtime.h>
#include <cuda_bf16.h>
#include <cuda_fp16.h>
#include <math.h>
#include <stdint.h>

#define NN 20000
#define EE 160000
#define OUTD 256
#define INDIM 256
#define NH 8

typedef unsigned long long ull;

// ---------------- scratch (device globals; no allocation allowed) ----------------
__device__ float g_K[NN * OUTD];
__device__ float g_Q[NN * OUTD];
__device__ float g_V[NN * OUTD];
__device__ float g_MK[NN * OUTD];
__device__ __half g_VC[(size_t)3 * NN * 512];  // per (etype,node): [0,256)=val fp16, [256,512)=cval fp16
__device__ float2 g_E[3 * EE * NH];      // (ea, eca) per edge-head
__device__ float2 g_S[3 * NN * NH];      // (sum_ea, sum_eca) per dst-head
// bf16 hi/lo splits for tensor-core GEMM
__device__ __nv_bfloat16 g_xhi[NN * INDIM];
__device__ __nv_bfloat16 g_xlo[NN * INDIM];
__device__ __nv_bfloat16 g_wthi[768 * INDIM];   // [out_col][k] transposed
__device__ __nv_bfloat16 g_wtlo[768 * INDIM];

// ---------------- helpers ----------------
__device__ __forceinline__ ull pack2(float a, float b) {
    ull r; asm("mov.b64 %0, {%1, %2};" : "=l"(r) : "f"(a), "f"(b)); return r;
}
__device__ __forceinline__ void fma2(ull& acc, ull a, ull b) {
    asm("fma.rn.f32x2 %0, %1, %2, %0;" : "+l"(acc) : "l"(a), "l"(b));
}
__device__ __forceinline__ float2 unpack2(ull v) {
    float2 f; asm("mov.b64 {%0, %1}, %2;" : "=f"(f.x), "=f"(f.y) : "l"(v)); return f;
}
__device__ __forceinline__ float dot4(float4 a, float4 b) {
    return a.x * b.x + a.y * b.y + a.z * b.z + a.w * b.w;
}
__device__ __forceinline__ void red_add_v4(float* p, float a, float b, float c, float d) {
    asm volatile("red.global.add.v4.f32 [%0], {%1,%2,%3,%4};"
                 :: "l"(p), "f"(a), "f"(b), "f"(c), "f"(d) : "memory");
}
__device__ __forceinline__ void red_add_v2(float2* p, float a, float b) {
    asm volatile("red.global.add.v2.f32 [%0], {%1,%2};"
                 :: "l"(p), "f"(a), "f"(b) : "memory");
}
__device__ __forceinline__ uint32_t smem_to_u32(const void* p) {
    uint32_t a;
    asm("{ .reg .u64 t; cvta.to.shared.u64 t, %1; cvt.u32.u64 %0, t; }" : "=r"(a) : "l"(p));
    return a;
}
__device__ __forceinline__ void ldsm_x4(uint32_t* r, uint32_t addr) {
    asm volatile("ldmatrix.sync.aligned.m8n8.x4.shared.b16 {%0,%1,%2,%3}, [%4];"
        : "=r"(r[0]), "=r"(r[1]), "=r"(r[2]), "=r"(r[3]) : "r"(addr));
}
__device__ __forceinline__ void mma_bf16(float* c, const uint32_t* a, const uint32_t* b) {
    asm volatile("mma.sync.aligned.m16n8k16.row.col.f32.bf16.bf16.f32 "
        "{%0,%1,%2,%3}, {%4,%5,%6,%7}, {%8,%9}, {%0,%1,%2,%3};"
        : "+f"(c[0]), "+f"(c[1]), "+f"(c[2]), "+f"(c[3])
        : "r"(a[0]), "r"(a[1]), "r"(a[2]), "r"(a[3]), "r"(b[0]), "r"(b[1]));
}
__device__ __forceinline__ void cp_async16(uint32_t dst, const void* src, int sz) {
    asm volatile("cp.async.ca.shared.global [%0], [%1], 16, %2;"
                 :: "r"(dst), "l"(src), "r"(sz) : "memory");
}
__device__ __forceinline__ float4 h4_to_f4(uint2 u) {
    __half2 a = *(__half2*)&u.x, b = *(__half2*)&u.y;
    float2 fa = __half22float2(a), fb = __half22float2(b);
    return make_float4(fa.x, fa.y, fb.x, fb.y);
}

// ---------------- kernel 0: zero accumulators ----------------
__global__ void zero_kernel(float* __restrict__ out) {
    int stride = gridDim.x * blockDim.x;
    for (int i = blockIdx.x * blockDim.x + threadIdx.x; i < NN * OUTD; i += stride)
        out[i] = 0.0f;
    float2 z2 = make_float2(0.f, 0.f);
    for (int i = blockIdx.x * blockDim.x + threadIdx.x; i < 3 * NN * NH; i += stride)
        g_S[i] = z2;
}

// ---------------- prep: fp32 -> bf16 hi/lo splits ----------------
__global__ void split_x_kernel(const float* __restrict__ x) {
    int i = blockIdx.x * blockDim.x + threadIdx.x;   // one float4 per thread
    if (i >= NN * INDIM / 4) return;
    float4 v = ((const float4*)x)[i];
    __nv_bfloat16 h[4], l[4];
    float f[4] = {v.x, v.y, v.z, v.w};
#pragma unroll
    for (int j = 0; j < 4; j++) {
        h[j] = __float2bfloat16(f[j]);
        l[j] = __float2bfloat16(f[j] - __bfloat162float(h[j]));
    }
    ((uint2*)g_xhi)[i] = *(uint2*)h;
    ((uint2*)g_xlo)[i] = *(uint2*)l;
}

// transpose + split W: g_wt[c][k] = W_sel[k][c%256]
__global__ void split_w_kernel(const float* __restrict__ Wk,
                               const float* __restrict__ Wq,
                               const float* __restrict__ Wv) {
    int i = blockIdx.x * blockDim.x + threadIdx.x;   // i = c*256 + k
    if (i >= 768 * INDIM) return;
    int c = i >> 8, k = i & 255;
    const float* W = (c < 256) ? Wk : ((c < 512) ? Wq : Wv);
    float v = W[k * 256 + (c & 255)];
    __nv_bfloat16 h = __float2bfloat16(v);
    __nv_bfloat16 l = __float2bfloat16(v - __bfloat162float(h));
    g_wthi[i] = h;
    g_wtlo[i] = l;
}

// ---------------- kernel 1: QKV GEMM via mma.sync bf16x3, cp.async double-buffered ----------------
// Block tile 128x128, 8 warps (2m x 4n), warp tile 64x32, K-chunk 32 (8 chunks), 2 stages.
#define STAGE_BYTES 40960
__global__ void __launch_bounds__(256, 2) gemm_mma(
    const float* __restrict__ bk, const float* __restrict__ bq, const float* __restrict__ bv)
{
    extern __shared__ __align__(16) unsigned char smdyn[];
    const int AHI = 0, ALO = 10240, BHI = 20480, BLO = 30720;

    int tid = threadIdx.x;
    int lane = tid & 31, wid = tid >> 5;
    int warp_m = wid >> 2;       // 0..1
    int warp_n = wid & 3;        // 0..3
    int mbase = blockIdx.y * 128;
    int nbg = blockIdx.x * 128;  // global col base in 0..767

    uint32_t sb = smem_to_u32(smdyn);

    float acc[4][4][4];
#pragma unroll
    for (int nt = 0; nt < 4; nt++)
#pragma unroll
        for (int mt = 0; mt < 4; mt++)
#pragma unroll
            for (int j = 0; j < 4; j++) acc[nt][mt][j] = 0.0f;

    // ---- async loader: thread t covers 16B segments c = t and c = t + 256 ----
#define LOAD_CHUNK(chunk, stage) do {                                               \
        int _k0 = (chunk) * 32;                                                     \
        uint32_t _s0 = sb + (stage) * STAGE_BYTES;                                  \
        _Pragma("unroll")                                                           \
        for (int _j = 0; _j < 2; _j++) {                                            \
            int _c = tid + _j * 256;                                                \
            int _row = _c >> 2, _seg = _c & 3;                                      \
            uint32_t _so = (uint32_t)(_row * 80 + _seg * 16);                       \
            int _gn = mbase + _row;                                                 \
            int _ok = (_gn < NN);                                                   \
            const unsigned char* _pah = (const unsigned char*)(g_xhi + (size_t)(_ok ? _gn : 0) * INDIM + _k0) + _seg * 16; \
            const unsigned char* _pal = (const unsigned char*)(g_xlo + (size_t)(_ok ? _gn : 0) * INDIM + _k0) + _seg * 16; \
            cp_async16(_s0 + AHI + _so, _pah, _ok ? 16 : 0);                        \
            cp_async16(_s0 + ALO + _so, _pal, _ok ? 16 : 0);                        \
            const unsigned char* _pbh = (const unsigned char*)(g_wthi + (size_t)(nbg + _row) * INDIM + _k0) + _seg * 16; \
            const unsigned char* _pbl = (const unsigned char*)(g_wtlo + (size_t)(nbg + _row) * INDIM + _k0) + _seg * 16; \
            cp_async16(_s0 + BHI + _so, _pbh, 16);                                  \
            cp_async16(_s0 + BLO + _so, _pbl, 16);                                  \
        }                                                                           \
        asm volatile("cp.async.commit_group;" ::: "memory");                        \
    } while (0)

    LOAD_CHUNK(0, 0);

    for (int chunk = 0; chunk < 8; chunk++) {
        if (chunk + 1 < 8) {
            LOAD_CHUNK(chunk + 1, (chunk + 1) & 1);
            asm volatile("cp.async.wait_group 1;" ::: "memory");
        } else {
            asm volatile("cp.async.wait_group 0;" ::: "memory");
        }
        __syncthreads();

        uint32_t s0 = sb + (chunk & 1) * STAGE_BYTES;
#pragma unroll
        for (int ks = 0; ks < 2; ks++) {
            uint32_t bh[2][4], bl[2][4];
            int boff = ks * 32 + ((lane >> 3) & 1) * 16;
#pragma unroll
            for (int np = 0; np < 2; np++) {
                int br = warp_n * 32 + np * 16 + ((lane >> 4) & 1) * 8 + (lane & 7);
                uint32_t baddr = s0 + BHI + (uint32_t)(br * 80) + boff;
                ldsm_x4(bh[np], baddr);
                ldsm_x4(bl[np], baddr + (BLO - BHI));
            }
            int aoff = ks * 32 + ((lane >> 4) & 1) * 16;
#pragma unroll
            for (int mt = 0; mt < 4; mt++) {
                uint32_t ah[4], al[4];
                uint32_t addr = s0 + AHI + (uint32_t)((warp_m * 64 + mt * 16 + (lane & 15)) * 80) + aoff;
                ldsm_x4(ah, addr);
                ldsm_x4(al, addr + (ALO - AHI));
#pragma unroll
                for (int np = 0; np < 2; np++)
#pragma unroll
                    for (int sub = 0; sub < 2; sub++) {
                        int nt = np * 2 + sub;
                        mma_bf16(acc[nt][mt], ah, &bh[np][sub * 2]);
                        mma_bf16(acc[nt][mt], ah, &bl[np][sub * 2]);
                        mma_bf16(acc[nt][mt], al, &bh[np][sub * 2]);
                    }
            }
        }
        __syncthreads();
    }

    // epilogue: direct float2 stores + bias
    int buf = nbg >> 8;
    int col0 = (nbg & 255) + warp_n * 32;
    float* outp = (buf == 0) ? g_K : ((buf == 1) ? g_Q : g_V);
    const float* bias = (buf == 0) ? bk : ((buf == 1) ? bq : bv);

#pragma unroll
    for (int mt = 0; mt < 4; mt++) {
        int r0 = mbase + warp_m * 64 + mt * 16 + (lane >> 2);
#pragma unroll
        for (int nt = 0; nt < 4; nt++) {
            int c = col0 + nt * 8 + (lane & 3) * 2;
            float2 bb = *(const float2*)&bias[c];
            if (r0 < NN) {
                float2 o = make_float2(acc[nt][mt][0] + bb.x, acc[nt][mt][1] + bb.y);
                *(float2*)&outp[(size_t)r0 * OUTD + c] = o;
            }
            if (r0 + 8 < NN) {
                float2 o = make_float2(acc[nt][mt][2] + bb.x, acc[nt][mt][3] + bb.y);
                *(float2*)&outp[(size_t)(r0 + 8) * OUTD + c] = o;
            }
        }
    }
}

// ---------------- kernel 2: node-level relation transforms ----------------
// MK stays fp32 (feeds logits); val/cval stored fp16 into g_VC.
__global__ void __launch_bounds__(288) transform_kernel(
    const float* __restrict__ msg, const float* __restrict__ msg_cau,
    const float* __restrict__ cau_filter, const float* __restrict__ time_emb,
    const int* __restrict__ cau_type)
{
    __shared__ float k_s[32][32];
    __shared__ float v_s[32][32];
    __shared__ float vt_s[32][32];
    __shared__ int ct_s[32];

    int h = blockIdx.y;
    int nodeBase = blockIdx.x * 32;
    int tid = threadIdx.x;

    for (int idx = tid; idx < 32 * 32; idx += 288) {
        int n = idx >> 5, dcol = idx & 31;
        int gn = nodeBase + n;
        float kv = 0.f, vv = 0.f;
        if (gn < NN) {
            kv = g_K[gn * OUTD + h * 32 + dcol];
            vv = g_V[gn * OUTD + h * 32 + dcol];
        }
        k_s[n][dcol] = kv;
        v_s[n][dcol] = vv;
        vt_s[n][dcol] = vv + time_emb[h * 32 + dcol];
    }
    for (int idx = tid; idx < 32; idx += 288) {
        int gn = nodeBase + idx;
        ct_s[idx] = (gn < NN) ? cau_type[gn] : -1;
    }
    __syncthreads();

    int wid = tid >> 5, lane = tid & 31;
    const float* mat;
    const float (*srcm)[32];
    float* outp_f = 0;
    __half* outp_h = 0;
    int myct = -1;
    if (wid < 3) {
        mat = cau_filter + (wid * NH + h) * 1024;
        srcm = k_s; outp_f = g_MK; myct = wid;
    } else if (wid < 6) {
        int e = wid - 3;
        mat = msg + (e * NH + h) * 1024;
        srcm = v_s; outp_h = g_VC + (size_t)e * NN * 512;      // val at offset 0
    } else {
        int e = wid - 6;
        mat = msg_cau + (e * NH + h) * 1024;
        srcm = vt_s; outp_h = g_VC + (size_t)e * NN * 512 + 256;  // cval at +256
    }

    ull m2[16];
#pragma unroll
    for (int i = 0; i < 16; i++)
        m2[i] = pack2(mat[(2 * i) * 32 + lane], mat[(2 * i + 1) * 32 + lane]);

    for (int n = 0; n < 32; n++) {
        int gn = nodeBase + n;
        if (gn >= NN) break;
        if (myct >= 0 && ct_s[n] != myct) continue;
        ull acc = 0ull;
        const ull* row = (const ull*)&srcm[n][0];
#pragma unroll
        for (int i = 0; i < 16; i++)
            fma2(acc, row[i], m2[i]);
        float2 f = unpack2(acc);
        float r = f.x + f.y;
        if (outp_f) outp_f[gn * OUTD + h * 32 + lane] = r;
        else        outp_h[(size_t)gn * 512 + h * 32 + lane] = __float2half(r);
    }
}

// ---------------- kernel 3: edge logits + softmax denominators ----------------
__global__ void __launch_bounds__(256) logits_kernel(
    const int* __restrict__ src, const int* __restrict__ dst,
    const float* __restrict__ pri, const float* __restrict__ pri_cau)
{
    int e = blockIdx.y;
    int edge = blockIdx.x * 8 + (threadIdx.x >> 5);
    if (edge >= EE) return;
    int lane = threadIdx.x & 31;
    int s = src[e * EE + edge];
    int d = dst[e * EE + edge];
    int off = lane * 4;

    const float* qp = g_Q + d * OUTD;
    const float* kp = g_K + s * OUTD;
    const float* mp = g_MK + s * OUTD;
    float4 qa = *(const float4*)(qp + off);
    float4 qb = *(const float4*)(qp + 128 + off);
    float4 ka = *(const float4*)(kp + off);
    float4 kb = *(const float4*)(kp + 128 + off);
    float4 ma = *(const float4*)(mp + off);
    float4 mb = *(const float4*)(mp + 128 + off);

    float p0 = dot4(qa, ka);
    float p1 = dot4(qb, kb);
    float m0 = dot4(qa, ma);
    float m1 = dot4(qb, mb);

#pragma unroll
    for (int sh = 1; sh <= 4; sh <<= 1) {
        p0 += __shfl_xor_sync(0xffffffffu, p0, sh);
        p1 += __shfl_xor_sync(0xffffffffu, p1, sh);
        m0 += __shfl_xor_sync(0xffffffffu, m0, sh);
        m1 += __shfl_xor_sync(0xffffffffu, m1, sh);
    }
    int g = lane >> 3;
    const float isdk = 0.17677669529663687f;  // 1/sqrt(32)
    float ea0 = __expf(p0 * pri[e * NH + g] * isdk);
    float ea1 = __expf(p1 * pri[e * NH + g + 4] * isdk);
    float ec0 = __expf(m0 * pri_cau[e * NH + g] * isdk);
    float ec1 = __expf(m1 * pri_cau[e * NH + g + 4] * isdk);

    int srcl = (lane & 3) * 8;
    float va0 = __shfl_sync(0xffffffffu, ea0, srcl);
    float va1 = __shfl_sync(0xffffffffu, ea1, srcl);
    float vc0 = __shfl_sync(0xffffffffu, ec0, srcl);
    float vc1 = __shfl_sync(0xffffffffu, ec1, srcl);

    if (lane < NH) {
        float ea = (lane < 4) ? va0 : va1;
        float ec = (lane < 4) ? vc0 : vc1;
        int eidx = e * EE + edge;
        g_E[eidx * NH + lane] = make_float2(ea, ec);
        red_add_v2(&g_S[(e * NN + d) * NH + lane], ea, ec);
    }
}

// ---------------- kernel 4: weighted aggregation (fp16 gathers) ----------------
__global__ void __launch_bounds__(256) aggregate_kernel(
    const int* __restrict__ src, const int* __restrict__ dst,
    const float* __restrict__ comb_pri, float* __restrict__ out)
{
    int e = blockIdx.y;
    int edge = blockIdx.x * 8 + (threadIdx.x >> 5);
    if (edge >= EE) return;
    int lane = threadIdx.x & 31;
    int s = src[e * EE + edge];
    int d = dst[e * EE + edge];
    int h0 = lane >> 3;
    int h1 = h0 + 4;
    int eidx = e * EE + edge;

    float2 eh0 = g_E[eidx * NH + h0];
    float2 eh1 = g_E[eidx * NH + h1];
    float2 s0 = g_S[(e * NN + d) * NH + h0];
    float2 s1 = g_S[(e * NN + d) * NH + h1];
    float wa0 = __fdividef(eh0.x, s0.x);
    float wc0 = __fdividef(eh0.y, s0.y);
    float wa1 = __fdividef(eh1.x, s1.x);
    float wc1 = __fdividef(eh1.y, s1.y);

    int off = lane * 4;
    const __half* vp = g_VC + ((size_t)e * NN + s) * 512;
    float4 v0 = h4_to_f4(*(const uint2*)(vp + off));
    float4 v1 = h4_to_f4(*(const uint2*)(vp + 128 + off));
    float4 c0 = h4_to_f4(*(const uint2*)(vp + 256 + off));
    float4 c1 = h4_to_f4(*(const uint2*)(vp + 384 + off));
    float4 b0 = *(const float4*)&comb_pri[e * OUTD + off];
    float4 b1 = *(const float4*)&comb_pri[e * OUTD + 128 + off];

    float r0 = wa0 * v0.x + wc0 * b0.x * c0.x;
    float r1 = wa0 * v0.y + wc0 * b0.y * c0.y;
    float r2 = wa0 * v0.z + wc0 * b0.z * c0.z;
    float r3 = wa0 * v0.w + wc0 * b0.w * c0.w;
    float r4 = wa1 * v1.x + wc1 * b1.x * c1.x;
    float r5 = wa1 * v1.y + wc1 * b1.y * c1.y;
    float r6 = wa1 * v1.z + wc1 * b1.z * c1.z;
    float r7 = wa1 * v1.w + wc1 * b1.w * c1.w;

    float* op = out + d * OUTD;
    red_add_v4(op + off, r0, r1, r2, r3);
    red_add_v4(op + 128 + off, r4, r5, r6, r7);
}

// ---------------- kernel 5: finalize (mean over 3 etypes + relu) ----------------
__global__ void finalize_kernel(float* __restrict__ out) {
    int i = blockIdx.x * blockDim.x + threadIdx.x;
    if (i < NN * OUTD) {
        float v = out[i] * (1.0f / 3.0f);
        out[i] = v > 0.0f ? v : 0.0f;
    }
}

// ---------------- launch ----------------
extern "C" void kernel_launch(void* const* d_in, const int* in_sizes, int n_in,
                              void* d_out, int out_size) {
    const float* x          = (const float*)d_in[0];
    const float* Wk         = (const float*)d_in[1];
    const float* bk         = (const float*)d_in[2];
    const float* Wq         = (const float*)d_in[3];
    const float* bq         = (const float*)d_in[4];
    const float* Wv         = (const float*)d_in[5];
    const float* bv         = (const float*)d_in[6];
    const float* pri        = (const float*)d_in[7];
    const float* msg        = (const float*)d_in[8];
    const float* pri_cau    = (const float*)d_in[9];
    const float* msg_cau    = (const float*)d_in[10];
    const float* comb_pri   = (const float*)d_in[11];
    const float* cau_filter = (const float*)d_in[12];
    const float* time_emb   = (const float*)d_in[13];
    const int*   cau_type   = (const int*)d_in[14];
    const int*   src        = (const int*)d_in[15];
    const int*   dst        = (const int*)d_in[16];
    float* out = (float*)d_out;

    zero_kernel<<<2048, 256>>>(out);

    split_x_kernel<<<(NN * INDIM / 4 + 255) / 256, 256>>>(x);
    split_w_kernel<<<768, 256>>>(Wk, Wq, Wv);

    cudaFuncSetAttribute(gemm_mma, cudaFuncAttributeMaxDynamicSharedMemorySize,
                         2 * STAGE_BYTES);
    gemm_mma<<<dim3(6, 157), 256, 2 * STAGE_BYTES>>>(bk, bq, bv);

    dim3 tgrid((NN + 31) / 32, NH);
    transform_kernel<<<tgrid, 288>>>(msg, msg_cau, cau_filter, time_emb, cau_type);

    dim3 egrid((EE + 7) / 8, 3);
    logits_kernel<<<egrid, 256>>>(src, dst, pri, pri_cau);
    aggregate_kernel<<<egrid, 256>>>(src, dst, comb_pri, out);

    finalize_kernel<<<(NN * OUTD + 255) / 256, 256>>>(out);
}